// round 3
// baseline (speedup 1.0000x reference)
#include <cuda_runtime.h>
#include <mma.h>
#include <cstdint>

using namespace nvcuda;

#define NPTS 40000
#define NSAMP 32
#define STOT (NPTS * NSAMP)     // 1,280,000
#define C0IN 38
#define C1 64
#define C2 64
#define C3 128
#define BNEPS 1e-5f
#define BLK 256
#define NWARP 8
#define TM 256                  // M-tile rows
#define NT256 (STOT / TM)       // 5000 tiles
#define LDX 72
#define LDW1 72
#define LDW2 136
#define LDQ 132

// ---------------- scratch (device globals) ---------------------------------
__device__ __align__(16) float g_A[NPTS * C1];
__device__ __align__(16) float g_B[NPTS * C1];
__device__ __align__(16) float g_pmax[NPTS * C3];
__device__ __align__(16) float g_pmin[NPTS * C3];

__device__ float g_sum0[C1], g_sq0[C1];
__device__ float g_sum1[C2], g_sq1[C2];
__device__ float g_sum2[C3], g_sq2[C3];
__device__ __align__(16) float g_a0[C1], g_c0[C1];
__device__ __align__(16) float g_a1[C2], g_c1[C2];
__device__ __align__(16) float g_a2[C3], g_c2[C3];

__global__ void k_zero() {
    int t = threadIdx.x;
    if (t < C1) { g_sum0[t] = 0.f; g_sq0[t] = 0.f; g_sum1[t] = 0.f; g_sq1[t] = 0.f; }
    if (t < C3) { g_sum2[t] = 0.f; g_sq2[t] = 0.f; }
}

__global__ void k_copy(const float* __restrict__ center,
                       const float* __restrict__ normal,
                       const int* __restrict__ offset,
                       float* __restrict__ out, int writeOffsetSlot) {
    int i = blockIdx.x * blockDim.x + threadIdx.x;
    int stride = gridDim.x * blockDim.x;
    for (; i < 2 * NPTS * 3; i += stride) {
        out[i] = (i < NPTS * 3) ? center[i] : normal[i - NPTS * 3];
    }
    if (writeOffsetSlot && blockIdx.x == 0 && threadIdx.x == 0) {
        out[2 * NPTS * 3 + NPTS * C3] = (float)offset[0];
    }
}

// ---------------- per-point precompute A = W0*x+b0, B = W0c*center ---------
__global__ void k_pre(const float* __restrict__ center,
                      const float* __restrict__ normal,
                      const float* __restrict__ feature,
                      const float* __restrict__ W0,
                      const float* __restrict__ b0) {
    __shared__ __align__(16) float Wt[C0IN * C1];
    __shared__ float xs[NWARP][C0IN];
    int tid = threadIdx.x;
    for (int i = tid; i < C0IN * C1; i += BLK) {
        int o = i / C0IN, c = i % C0IN;
        Wt[c * C1 + o] = W0[i];
    }
    __syncthreads();
    int w = tid >> 5, lane = tid & 31;
    int o0 = 2 * lane;
    float bias0 = b0[o0], bias1 = b0[o0 + 1];
    int wg = blockIdx.x * NWARP + w, nW = gridDim.x * NWARP;
    for (int n = wg; n < NPTS; n += nW) {
        {
            float v;
            if (lane < 3)      v = center[n * 3 + lane];
            else if (lane < 6) v = normal[n * 3 + lane - 3];
            else               v = feature[n * 32 + lane - 6];
            xs[w][lane] = v;
            if (lane < C0IN - 32) xs[w][32 + lane] = feature[n * 32 + 26 + lane];
        }
        __syncwarp();
        float a0 = 0.f, a1 = 0.f, bp0 = 0.f, bp1 = 0.f;
        #pragma unroll
        for (int c = 0; c < C0IN; ++c) {
            float2 wv = *(const float2*)&Wt[c * C1 + o0];
            float x = xs[w][c];
            a0 += wv.x * x; a1 += wv.y * x;
            if (c < 3) { bp0 += wv.x * x; bp1 += wv.y * x; }
        }
        *(float2*)&g_A[n * C1 + o0] = make_float2(a0 + bias0, a1 + bias1);
        *(float2*)&g_B[n * C1 + o0] = make_float2(bp0, bp1);
        __syncwarp();
    }
}

// ---------------- layer-0 stats: y0 = A[j]-B[n] ----------------------------
__global__ void k_l0stats(const int* __restrict__ gidx) {
    __shared__ float sS[C1], sQ[C1];
    int tid = threadIdx.x;
    if (tid < C1) { sS[tid] = 0.f; sQ[tid] = 0.f; }
    __syncthreads();
    int w = tid >> 5, lane = tid & 31, c0 = 2 * lane;
    float s0 = 0.f, s1 = 0.f, q0 = 0.f, q1 = 0.f;
    int wg = blockIdx.x * NWARP + w, nW = gridDim.x * NWARP;
    for (int n = wg; n < NPTS; n += nW) {
        float2 bv = *(const float2*)&g_B[n * C1 + c0];
        int js = gidx[n * NSAMP + lane];
        #pragma unroll
        for (int s = 0; s < NSAMP; ++s) {
            int j = __shfl_sync(0xffffffffu, js, s);
            float2 av = *(const float2*)&g_A[j * C1 + c0];
            float y0 = av.x - bv.x, y1v = av.y - bv.y;
            s0 += y0; s1 += y1v; q0 += y0 * y0; q1 += y1v * y1v;
        }
    }
    atomicAdd(&sS[c0], s0); atomicAdd(&sS[c0 + 1], s1);
    atomicAdd(&sQ[c0], q0); atomicAdd(&sQ[c0 + 1], q1);
    __syncthreads();
    if (tid < C1) { atomicAdd(&g_sum0[tid], sS[tid]); atomicAdd(&g_sq0[tid], sQ[tid]); }
}

__global__ void k_fin0(const float* __restrict__ g, const float* __restrict__ be) {
    int t = threadIdx.x;
    if (t < C1) {
        float inv = 1.f / (float)STOT;
        float mean = g_sum0[t] * inv;
        float var = g_sq0[t] * inv - mean * mean;
        float a = g[t] * rsqrtf(var + BNEPS);
        g_a0[t] = a;
        g_c0[t] = fmaf(-a, mean, be[t]);
    }
}
// stats1 were accumulated on y1 WITH bias; fold c1 = a*(b1-mean)+be
__global__ void k_fin1(const float* __restrict__ g, const float* __restrict__ be,
                       const float* __restrict__ b1) {
    int t = threadIdx.x;
    if (t < C2) {
        float inv = 1.f / (float)STOT;
        float mean = g_sum1[t] * inv;
        float var = g_sq1[t] * inv - mean * mean;
        float a = g[t] * rsqrtf(var + BNEPS);
        g_a1[t] = a;
        g_c1[t] = fmaf(a, b1[t] - mean, be[t]);
    }
}
__global__ void k_fin2(const float* __restrict__ g, const float* __restrict__ be) {
    int t = threadIdx.x;
    if (t < C3) {
        float inv = 1.f / (float)STOT;
        float mean = g_sum2[t] * inv;
        float var = g_sq2[t] * inv - mean * mean;
        float a = g[t] * rsqrtf(var + BNEPS);
        g_a2[t] = a;
        g_c2[t] = fmaf(-a, mean, be[t]);
    }
}

// ---------------- layer-1 stats: build y1 tile in smem, reduce, discard ----
__global__ void __launch_bounds__(512, 2)
k_l1stats(const int* __restrict__ gidx, const float* __restrict__ W1,
          const float* __restrict__ b1) {
    extern __shared__ float sm[];
    float* X  = sm;                 // [TM][LDX], reused for y1
    float* Ws = sm + TM * LDX;      // [C1][LDW1]
    __shared__ float aS[C1], cS[C1], sS[C2], sQ[C2];
    int tid = threadIdx.x;
    for (int i = tid; i < C1 * C2; i += 512) {
        int o = i / C1, c = i % C1;
        Ws[c * LDW1 + o] = wmma::__float_to_tf32(W1[i]);
    }
    if (tid < C1) { aS[tid] = g_a0[tid]; cS[tid] = g_c0[tid]; sS[tid] = 0.f; sQ[tid] = 0.f; }
    __syncthreads();

    int w = tid >> 5, wm = w >> 1, wn = w & 1;
    int col4 = (tid & 15) * 4, rg = tid >> 4;       // 32 row-groups of 8 rows
    float4 b1v = *(const float4*)&b1[col4];
    float4 sum4 = make_float4(0, 0, 0, 0), sq4 = make_float4(0, 0, 0, 0);

    for (int t = blockIdx.x; t < NT256; t += gridDim.x) {
        int s0 = t * TM;
        for (int idx = tid; idx < TM * 16; idx += 512) {
            int r = idx >> 4; int cg = (idx & 15) * 4;
            int s = s0 + r; int j = gidx[s]; int n = s >> 5;
            float4 av = *(const float4*)&g_A[j * C1 + cg];
            float4 b4 = *(const float4*)&g_B[n * C1 + cg];
            X[r * LDX + cg + 0] = wmma::__float_to_tf32(fmaxf(0.f, fmaf(aS[cg + 0], av.x - b4.x, cS[cg + 0])));
            X[r * LDX + cg + 1] = wmma::__float_to_tf32(fmaxf(0.f, fmaf(aS[cg + 1], av.y - b4.y, cS[cg + 1])));
            X[r * LDX + cg + 2] = wmma::__float_to_tf32(fmaxf(0.f, fmaf(aS[cg + 2], av.z - b4.z, cS[cg + 2])));
            X[r * LDX + cg + 3] = wmma::__float_to_tf32(fmaxf(0.f, fmaf(aS[cg + 3], av.w - b4.w, cS[cg + 3])));
        }
        __syncthreads();

        wmma::fragment<wmma::accumulator, 16, 16, 8, float> acc[2][2];
        #pragma unroll
        for (int i = 0; i < 2; ++i)
            #pragma unroll
            for (int jj = 0; jj < 2; ++jj) wmma::fill_fragment(acc[i][jj], 0.f);
        #pragma unroll
        for (int k = 0; k < 8; ++k) {
            wmma::fragment<wmma::matrix_a, 16, 16, 8, wmma::precision::tf32, wmma::row_major> fa0, fa1;
            wmma::fragment<wmma::matrix_b, 16, 16, 8, wmma::precision::tf32, wmma::row_major> fb0, fb1;
            wmma::load_matrix_sync(fa0, X + (wm * 32 + 0) * LDX + k * 8, LDX);
            wmma::load_matrix_sync(fa1, X + (wm * 32 + 16) * LDX + k * 8, LDX);
            wmma::load_matrix_sync(fb0, Ws + (k * 8) * LDW1 + wn * 32 + 0, LDW1);
            wmma::load_matrix_sync(fb1, Ws + (k * 8) * LDW1 + wn * 32 + 16, LDW1);
            wmma::mma_sync(acc[0][0], fa0, fb0, acc[0][0]);
            wmma::mma_sync(acc[0][1], fa0, fb1, acc[0][1]);
            wmma::mma_sync(acc[1][0], fa1, fb0, acc[1][0]);
            wmma::mma_sync(acc[1][1], fa1, fb1, acc[1][1]);
        }
        __syncthreads();   // all warps done reading X before overwrite
        #pragma unroll
        for (int i = 0; i < 2; ++i)
            #pragma unroll
            for (int jj = 0; jj < 2; ++jj)
                wmma::store_matrix_sync(X + (wm * 32 + i * 16) * LDX + wn * 32 + jj * 16,
                                        acc[i][jj], LDX, wmma::mem_row_major);
        __syncthreads();
        #pragma unroll
        for (int r8 = 0; r8 < 8; ++r8) {
            int r = rg * 8 + r8;
            float4 v = *(float4*)&X[r * LDX + col4];
            v.x += b1v.x; v.y += b1v.y; v.z += b1v.z; v.w += b1v.w;
            sum4.x += v.x; sum4.y += v.y; sum4.z += v.z; sum4.w += v.w;
            sq4.x += v.x * v.x; sq4.y += v.y * v.y; sq4.z += v.z * v.z; sq4.w += v.w * v.w;
        }
        __syncthreads();
    }
    atomicAdd(&sS[col4 + 0], sum4.x); atomicAdd(&sS[col4 + 1], sum4.y);
    atomicAdd(&sS[col4 + 2], sum4.z); atomicAdd(&sS[col4 + 3], sum4.w);
    atomicAdd(&sQ[col4 + 0], sq4.x);  atomicAdd(&sQ[col4 + 1], sq4.y);
    atomicAdd(&sQ[col4 + 2], sq4.z);  atomicAdd(&sQ[col4 + 3], sq4.w);
    __syncthreads();
    if (tid < C2) { atomicAdd(&g_sum1[tid], sS[tid]); atomicAdd(&g_sq1[tid], sQ[tid]); }
}

// ---------------- fused layer1+layer2: x1 -> y1 -> x2 -> y2 + stats + pool -
__global__ void __launch_bounds__(512, 1)
k_l23(const int* __restrict__ gidx, const float* __restrict__ W1,
      const float* __restrict__ W2, const float* __restrict__ b2) {
    extern __shared__ float sm[];
    float* X1  = sm;                         // [TM][LDX]
    float* X2  = sm + TM * LDX;              // [TM][LDX]  (y1 then x2)
    float* W1s = sm + 2 * TM * LDX;          // [C1][LDW1]
    float* W2s = W1s + C1 * LDW1;            // [C2][LDW2]
    float* Q   = sm;                         // [TM][LDQ] y2 (overlays X1+X2)
    __shared__ float aS0[C1], cS0[C1], aS1[C2], cS1[C2];
    __shared__ float sS[C3], sQs[C3];
    __shared__ __align__(16) float sMx[16][C3];
    __shared__ __align__(16) float sMn[16][C3];
    int tid = threadIdx.x;
    for (int i = tid; i < C1 * C2; i += 512) {
        int o = i / C1, c = i % C1;
        W1s[c * LDW1 + o] = wmma::__float_to_tf32(W1[i]);
    }
    for (int i = tid; i < C2 * C3; i += 512) {
        int o = i / C2, c = i % C2;
        W2s[c * LDW2 + o] = wmma::__float_to_tf32(W2[i]);
    }
    if (tid < C1) { aS0[tid] = g_a0[tid]; cS0[tid] = g_c0[tid];
                    aS1[tid] = g_a1[tid]; cS1[tid] = g_c1[tid]; }
    if (tid < C3) { sS[tid] = 0.f; sQs[tid] = 0.f; }
    __syncthreads();

    int w = tid >> 5, wm = w >> 1, wn = w & 1;
    int col4 = (tid & 31) * 4, rg = tid >> 5;      // 16 row-groups of 16 rows
    float4 b2v = *(const float4*)&b2[col4];
    float4 sum4 = make_float4(0, 0, 0, 0), sq4 = make_float4(0, 0, 0, 0);

    for (int t = blockIdx.x; t < NT256; t += gridDim.x) {
        int s0 = t * TM;
        // ---- stage x1 ----
        for (int idx = tid; idx < TM * 16; idx += 512) {
            int r = idx >> 4; int cg = (idx & 15) * 4;
            int s = s0 + r; int j = gidx[s]; int n = s >> 5;
            float4 av = *(const float4*)&g_A[j * C1 + cg];
            float4 b4 = *(const float4*)&g_B[n * C1 + cg];
            X1[r * LDX + cg + 0] = wmma::__float_to_tf32(fmaxf(0.f, fmaf(aS0[cg + 0], av.x - b4.x, cS0[cg + 0])));
            X1[r * LDX + cg + 1] = wmma::__float_to_tf32(fmaxf(0.f, fmaf(aS0[cg + 1], av.y - b4.y, cS0[cg + 1])));
            X1[r * LDX + cg + 2] = wmma::__float_to_tf32(fmaxf(0.f, fmaf(aS0[cg + 2], av.z - b4.z, cS0[cg + 2])));
            X1[r * LDX + cg + 3] = wmma::__float_to_tf32(fmaxf(0.f, fmaf(aS0[cg + 3], av.w - b4.w, cS0[cg + 3])));
        }
        __syncthreads();
        // ---- GEMM1: y1 = X1 * W1^T (no bias) -> X2 ----
        {
            wmma::fragment<wmma::accumulator, 16, 16, 8, float> acc[2][2];
            #pragma unroll
            for (int i = 0; i < 2; ++i)
                #pragma unroll
                for (int jj = 0; jj < 2; ++jj) wmma::fill_fragment(acc[i][jj], 0.f);
            #pragma unroll
            for (int k = 0; k < 8; ++k) {
                wmma::fragment<wmma::matrix_a, 16, 16, 8, wmma::precision::tf32, wmma::row_major> fa0, fa1;
                wmma::fragment<wmma::matrix_b, 16, 16, 8, wmma::precision::tf32, wmma::row_major> fb0, fb1;
                wmma::load_matrix_sync(fa0, X1 + (wm * 32 + 0) * LDX + k * 8, LDX);
                wmma::load_matrix_sync(fa1, X1 + (wm * 32 + 16) * LDX + k * 8, LDX);
                wmma::load_matrix_sync(fb0, W1s + (k * 8) * LDW1 + wn * 32 + 0, LDW1);
                wmma::load_matrix_sync(fb1, W1s + (k * 8) * LDW1 + wn * 32 + 16, LDW1);
                wmma::mma_sync(acc[0][0], fa0, fb0, acc[0][0]);
                wmma::mma_sync(acc[0][1], fa0, fb1, acc[0][1]);
                wmma::mma_sync(acc[1][0], fa1, fb0, acc[1][0]);
                wmma::mma_sync(acc[1][1], fa1, fb1, acc[1][1]);
            }
            #pragma unroll
            for (int i = 0; i < 2; ++i)
                #pragma unroll
                for (int jj = 0; jj < 2; ++jj)
                    wmma::store_matrix_sync(X2 + (wm * 32 + i * 16) * LDX + wn * 32 + jj * 16,
                                            acc[i][jj], LDX, wmma::mem_row_major);
        }
        __syncthreads();
        // ---- BN1 + relu in place: x2 = relu(a1*y1_nb + c1) ----
        for (int idx = tid; idx < TM * 16; idx += 512) {
            int r = idx >> 4; int cg = (idx & 15) * 4;
            float4 v = *(float4*)&X2[r * LDX + cg];
            X2[r * LDX + cg + 0] = wmma::__float_to_tf32(fmaxf(0.f, fmaf(aS1[cg + 0], v.x, cS1[cg + 0])));
            X2[r * LDX + cg + 1] = wmma::__float_to_tf32(fmaxf(0.f, fmaf(aS1[cg + 1], v.y, cS1[cg + 1])));
            X2[r * LDX + cg + 2] = wmma::__float_to_tf32(fmaxf(0.f, fmaf(aS1[cg + 2], v.z, cS1[cg + 2])));
            X2[r * LDX + cg + 3] = wmma::__float_to_tf32(fmaxf(0.f, fmaf(aS1[cg + 3], v.w, cS1[cg + 3])));
        }
        __syncthreads();
        // ---- GEMM2: y2 = X2 * W2^T ----
        wmma::fragment<wmma::accumulator, 16, 16, 8, float> acc2[2][4];
        #pragma unroll
        for (int i = 0; i < 2; ++i)
            #pragma unroll
            for (int jj = 0; jj < 4; ++jj) wmma::fill_fragment(acc2[i][jj], 0.f);
        #pragma unroll
        for (int k = 0; k < 8; ++k) {
            wmma::fragment<wmma::matrix_a, 16, 16, 8, wmma::precision::tf32, wmma::row_major> fa0, fa1;
            wmma::load_matrix_sync(fa0, X2 + (wm * 32 + 0) * LDX + k * 8, LDX);
            wmma::load_matrix_sync(fa1, X2 + (wm * 32 + 16) * LDX + k * 8, LDX);
            #pragma unroll
            for (int jj = 0; jj < 4; ++jj) {
                wmma::fragment<wmma::matrix_b, 16, 16, 8, wmma::precision::tf32, wmma::row_major> fb;
                wmma::load_matrix_sync(fb, W2s + (k * 8) * LDW2 + wn * 64 + jj * 16, LDW2);
                wmma::mma_sync(acc2[0][jj], fa0, fb, acc2[0][jj]);
                wmma::mma_sync(acc2[1][jj], fa1, fb, acc2[1][jj]);
            }
        }
        __syncthreads();   // all reads of X1/X2 done; Q overlays them
        #pragma unroll
        for (int i = 0; i < 2; ++i)
            #pragma unroll
            for (int jj = 0; jj < 4; ++jj)
                wmma::store_matrix_sync(Q + (wm * 32 + i * 16) * LDQ + wn * 64 + jj * 16,
                                        acc2[i][jj], LDQ, wmma::mem_row_major);
        __syncthreads();
        // ---- epilogue: bias + stats + per-16-row extrema ----
        {
            float4 mx = make_float4(-1e30f, -1e30f, -1e30f, -1e30f);
            float4 mn = make_float4(1e30f, 1e30f, 1e30f, 1e30f);
            #pragma unroll
            for (int r16 = 0; r16 < 16; ++r16) {
                int r = rg * 16 + r16;
                float4 v = *(float4*)&Q[r * LDQ + col4];
                v.x += b2v.x; v.y += b2v.y; v.z += b2v.z; v.w += b2v.w;
                sum4.x += v.x; sum4.y += v.y; sum4.z += v.z; sum4.w += v.w;
                sq4.x += v.x * v.x; sq4.y += v.y * v.y; sq4.z += v.z * v.z; sq4.w += v.w * v.w;
                mx.x = fmaxf(mx.x, v.x); mx.y = fmaxf(mx.y, v.y);
                mx.z = fmaxf(mx.z, v.z); mx.w = fmaxf(mx.w, v.w);
                mn.x = fminf(mn.x, v.x); mn.y = fminf(mn.y, v.y);
                mn.z = fminf(mn.z, v.z); mn.w = fminf(mn.w, v.w);
            }
            *(float4*)&sMx[rg][col4] = mx;
            *(float4*)&sMn[rg][col4] = mn;
        }
        __syncthreads();
        // 8 points x 128 cols = 1024 items over 512 threads
        #pragma unroll
        for (int it = 0; it < 2; ++it) {
            int item = tid + it * 512;
            int p = item >> 7, col = item & 127;
            float m0 = fmaxf(sMx[2 * p][col], sMx[2 * p + 1][col]);
            float m1 = fminf(sMn[2 * p][col], sMn[2 * p + 1][col]);
            int n = t * 8 + p;
            g_pmax[n * C3 + col] = m0;
            g_pmin[n * C3 + col] = m1;
        }
        __syncthreads();
    }
    atomicAdd(&sS[col4 + 0], sum4.x); atomicAdd(&sS[col4 + 1], sum4.y);
    atomicAdd(&sS[col4 + 2], sum4.z); atomicAdd(&sS[col4 + 3], sum4.w);
    atomicAdd(&sQs[col4 + 0], sq4.x); atomicAdd(&sQs[col4 + 1], sq4.y);
    atomicAdd(&sQs[col4 + 2], sq4.z); atomicAdd(&sQs[col4 + 3], sq4.w);
    __syncthreads();
    if (tid < C3) { atomicAdd(&g_sum2[tid], sS[tid]); atomicAdd(&g_sq2[tid], sQs[tid]); }
}

// ---------------- epilogue: BN2+relu on pooled extrema ---------------------
__global__ void k_poolapply(float* __restrict__ out) {
    int idx = blockIdx.x * blockDim.x + threadIdx.x;
    if (idx >= NPTS * (C3 / 4)) return;
    int n = idx >> 5, cg = (idx & 31) * 4;
    float4 a = *(const float4*)&g_a2[cg];
    float4 c = *(const float4*)&g_c2[cg];
    float4 mx = *(const float4*)&g_pmax[n * C3 + cg];
    float4 mn = *(const float4*)&g_pmin[n * C3 + cg];
    float4 o;
    o.x = fmaxf(0.f, fmaf(a.x, (a.x > 0.f) ? mx.x : mn.x, c.x));
    o.y = fmaxf(0.f, fmaf(a.y, (a.y > 0.f) ? mx.y : mn.y, c.y));
    o.z = fmaxf(0.f, fmaf(a.z, (a.z > 0.f) ? mx.z : mn.z, c.z));
    o.w = fmaxf(0.f, fmaf(a.w, (a.w > 0.f) ? mx.w : mn.w, c.w));
    *(float4*)&out[(size_t)n * C3 + cg] = o;
}

// ---------------- host entry ------------------------------------------------
extern "C" void kernel_launch(void* const* d_in, const int* in_sizes, int n_in,
                              void* d_out, int out_size) {
    const float* center  = (const float*)d_in[0];
    const float* normal  = (const float*)d_in[1];
    const float* feature = (const float*)d_in[2];
    const int*   offset  = (const int*)d_in[3];
    const int*   gidx    = (const int*)d_in[4];
    const float* W0 = (const float*)d_in[5];
    const float* b0 = (const float*)d_in[6];
    const float* g0 = (const float*)d_in[7];
    const float* be0 = (const float*)d_in[8];
    const float* W1 = (const float*)d_in[9];
    const float* b1 = (const float*)d_in[10];
    const float* g1 = (const float*)d_in[11];
    const float* be1 = (const float*)d_in[12];
    const float* W2 = (const float*)d_in[13];
    const float* b2 = (const float*)d_in[14];
    const float* g2 = (const float*)d_in[15];
    const float* be2 = (const float*)d_in[16];

    float* out = (float*)d_out;
    bool full = (out_size >= 2 * NPTS * 3 + NPTS * C3 + 1);
    float* featBase = full ? out + 2 * NPTS * 3 : out;

    const int SM_L1  = (TM * LDX + C1 * LDW1) * 4;                       // 92160 B
    const int SM_L23 = (2 * TM * LDX + C1 * LDW1 + C2 * LDW2) * 4;       // 200704 B
    cudaFuncSetAttribute(k_l1stats, cudaFuncAttributeMaxDynamicSharedMemorySize, SM_L1);
    cudaFuncSetAttribute(k_l23, cudaFuncAttributeMaxDynamicSharedMemorySize, SM_L23);

    k_zero<<<1, 128>>>();
    if (full) k_copy<<<256, 256>>>(center, normal, offset, out, 1);

    k_pre<<<160, BLK>>>(center, normal, feature, W0, b0);
    k_l0stats<<<1184, BLK>>>(gidx);
    k_fin0<<<1, 64>>>(g0, be0);
    k_l1stats<<<296, 512, SM_L1>>>(gidx, W1, b1);
    k_fin1<<<1, 64>>>(g1, be1, b1);
    k_l23<<<148, 512, SM_L23>>>(gidx, W1, W2, b2);
    k_fin2<<<1, 128>>>(g2, be2);
    k_poolapply<<<5000, BLK>>>(featBase);
}

// round 5
// speedup vs baseline: 1.9029x; 1.9029x over previous
#include <cuda_runtime.h>
#include <cstdint>

#define NPTS 40000
#define NSAMP 32
#define STOT (NPTS * NSAMP)     // 1,280,000
#define C0IN 38
#define C1 64
#define C2 64
#define C3 128
#define BNEPS 1e-5f
#define BLK 256
#define NWARP 8
#define TM 128
#define NT1 (STOT / TM)         // 10000 tiles
#define LDS1 68                 // smem leading dim (floats), conflict-free
#define BUFSZ (TM * LDS1)

// ---------------- scratch ---------------------------------------------------
__device__ __align__(16) float g_A[NPTS * C1];
__device__ __align__(16) float g_B[NPTS * C1];
__device__ __align__(16) float g_y1[(size_t)STOT * C2];
__device__ __align__(16) float g_pmax[NPTS * C3];
__device__ __align__(16) float g_pmin[NPTS * C3];

__device__ float g_sum0[C1], g_sq0[C1];
__device__ float g_sum1[C2], g_sq1[C2];
__device__ float g_sum2[C3], g_sq2[C3];
__device__ __align__(16) float g_a0[C1], g_c0[C1];
__device__ __align__(16) float g_a1[C2], g_c1[C2];
__device__ __align__(16) float g_a2[C3], g_c2[C3];

// ---------------- helpers ---------------------------------------------------
__device__ __forceinline__ float tf32r(float v) {
    uint32_t u = __float_as_uint(v);
    asm("cvt.rna.tf32.f32 %0, %0;" : "+r"(u));
    return __uint_as_float(u);
}
__device__ __forceinline__ void mma8(float* d, const uint32_t* a, const uint32_t* b) {
    asm volatile(
        "mma.sync.aligned.m16n8k8.row.col.f32.tf32.tf32.f32 "
        "{%0,%1,%2,%3}, {%4,%5,%6,%7}, {%8,%9}, {%0,%1,%2,%3};"
        : "+f"(d[0]), "+f"(d[1]), "+f"(d[2]), "+f"(d[3])
        : "r"(a[0]), "r"(a[1]), "r"(a[2]), "r"(a[3]), "r"(b[0]), "r"(b[1]));
}

__global__ void k_zero() {
    int t = threadIdx.x;
    if (t < C1) { g_sum0[t] = 0.f; g_sq0[t] = 0.f; g_sum1[t] = 0.f; g_sq1[t] = 0.f; }
    if (t < C3) { g_sum2[t] = 0.f; g_sq2[t] = 0.f; }
}

__global__ void k_copy(const float* __restrict__ center,
                       const float* __restrict__ normal,
                       const int* __restrict__ offset,
                       float* __restrict__ out, int writeOffsetSlot) {
    int i = blockIdx.x * blockDim.x + threadIdx.x;
    int stride = gridDim.x * blockDim.x;
    for (; i < 2 * NPTS * 3; i += stride) {
        out[i] = (i < NPTS * 3) ? center[i] : normal[i - NPTS * 3];
    }
    if (writeOffsetSlot && blockIdx.x == 0 && threadIdx.x == 0) {
        out[2 * NPTS * 3 + NPTS * C3] = (float)offset[0];
    }
}

// ---------------- per-point precompute A = W0*x+b0, B = W0c*center ---------
__global__ void k_pre(const float* __restrict__ center,
                      const float* __restrict__ normal,
                      const float* __restrict__ feature,
                      const float* __restrict__ W0,
                      const float* __restrict__ b0) {
    __shared__ __align__(16) float Wt[C0IN * C1];
    __shared__ float xs[NWARP][C0IN];
    int tid = threadIdx.x;
    for (int i = tid; i < C0IN * C1; i += BLK) {
        int o = i / C0IN, c = i % C0IN;
        Wt[c * C1 + o] = W0[i];
    }
    __syncthreads();
    int w = tid >> 5, lane = tid & 31;
    int o0 = 2 * lane;
    float bias0 = b0[o0], bias1 = b0[o0 + 1];
    int wg = blockIdx.x * NWARP + w, nW = gridDim.x * NWARP;
    for (int n = wg; n < NPTS; n += nW) {
        {
            float v;
            if (lane < 3)      v = center[n * 3 + lane];
            else if (lane < 6) v = normal[n * 3 + lane - 3];
            else               v = feature[n * 32 + lane - 6];
            xs[w][lane] = v;
            if (lane < C0IN - 32) xs[w][32 + lane] = feature[n * 32 + 26 + lane];
        }
        __syncwarp();
        float a0 = 0.f, a1 = 0.f, bp0 = 0.f, bp1 = 0.f;
        #pragma unroll
        for (int c = 0; c < C0IN; ++c) {
            float2 wv = *(const float2*)&Wt[c * C1 + o0];
            float x = xs[w][c];
            a0 += wv.x * x; a1 += wv.y * x;
            if (c < 3) { bp0 += wv.x * x; bp1 += wv.y * x; }
        }
        *(float2*)&g_A[n * C1 + o0] = make_float2(a0 + bias0, a1 + bias1);
        *(float2*)&g_B[n * C1 + o0] = make_float2(bp0, bp1);
        __syncwarp();
    }
}

// ---------------- layer-0 stats: y0 = A[j]-B[n] ----------------------------
__global__ void k_l0stats(const int* __restrict__ gidx) {
    __shared__ float sS[C1], sQ[C1];
    int tid = threadIdx.x;
    if (tid < C1) { sS[tid] = 0.f; sQ[tid] = 0.f; }
    __syncthreads();
    int w = tid >> 5, lane = tid & 31, c0 = 2 * lane;
    float s0 = 0.f, s1 = 0.f, q0 = 0.f, q1 = 0.f;
    int wg = blockIdx.x * NWARP + w, nW = gridDim.x * NWARP;
    for (int n = wg; n < NPTS; n += nW) {
        float2 bv = *(const float2*)&g_B[n * C1 + c0];
        int js = gidx[n * NSAMP + lane];
        #pragma unroll
        for (int s = 0; s < NSAMP; ++s) {
            int j = __shfl_sync(0xffffffffu, js, s);
            float2 av = *(const float2*)&g_A[j * C1 + c0];
            float y0 = av.x - bv.x, y1v = av.y - bv.y;
            s0 += y0; s1 += y1v; q0 += y0 * y0; q1 += y1v * y1v;
        }
    }
    atomicAdd(&sS[c0], s0); atomicAdd(&sS[c0 + 1], s1);
    atomicAdd(&sQ[c0], q0); atomicAdd(&sQ[c0 + 1], q1);
    __syncthreads();
    if (tid < C1) { atomicAdd(&g_sum0[tid], sS[tid]); atomicAdd(&g_sq0[tid], sQ[tid]); }
}

__global__ void k_fin0(const float* __restrict__ g, const float* __restrict__ be) {
    int t = threadIdx.x;
    if (t < C1) {
        float inv = 1.f / (float)STOT;
        float mean = g_sum0[t] * inv;
        float var = g_sq0[t] * inv - mean * mean;
        float a = g[t] * rsqrtf(var + BNEPS);
        g_a0[t] = a;
        g_c0[t] = fmaf(-a, mean, be[t]);
    }
}
__global__ void k_fin1(const float* __restrict__ g, const float* __restrict__ be) {
    int t = threadIdx.x;
    if (t < C2) {
        float inv = 1.f / (float)STOT;
        float mean = g_sum1[t] * inv;
        float var = g_sq1[t] * inv - mean * mean;
        float a = g[t] * rsqrtf(var + BNEPS);
        g_a1[t] = a;
        g_c1[t] = fmaf(-a, mean, be[t]);
    }
}
__global__ void k_fin2(const float* __restrict__ g, const float* __restrict__ be) {
    int t = threadIdx.x;
    if (t < C3) {
        float inv = 1.f / (float)STOT;
        float mean = g_sum2[t] * inv;
        float var = g_sq2[t] * inv - mean * mean;
        float a = g[t] * rsqrtf(var + BNEPS);
        g_a2[t] = a;
        g_c2[t] = fmaf(-a, mean, be[t]);
    }
}

// ---------------- layer1: gather -> BN0+relu -> mma tf32 -> y1 + stats -----
// 256 thr, 8 warps: wm = w>>2 (64 rows), wn = w&3 (16 cols). Bias b1 absorbed.
__device__ __forceinline__ void stage1(float* __restrict__ Xb, int tile, int tid,
                                       const int* __restrict__ gidx,
                                       const float* aS, const float* cS) {
    int r = tid >> 1, ch = (tid & 1) * 8;
    int s = tile * TM + r;
    int j = gidx[s];
    int n = s >> 5;
    float* row = Xb + r * LDS1;
    #pragma unroll
    for (int q = 0; q < 8; ++q) {
        int c4 = (ch + q) * 4;
        float4 av = *(const float4*)&g_A[j * C1 + c4];
        float4 bv = *(const float4*)&g_B[n * C1 + c4];
        row[c4 + 0] = tf32r(fmaxf(0.f, fmaf(aS[c4 + 0], av.x - bv.x, cS[c4 + 0])));
        row[c4 + 1] = tf32r(fmaxf(0.f, fmaf(aS[c4 + 1], av.y - bv.y, cS[c4 + 1])));
        row[c4 + 2] = tf32r(fmaxf(0.f, fmaf(aS[c4 + 2], av.z - bv.z, cS[c4 + 2])));
        row[c4 + 3] = tf32r(fmaxf(0.f, fmaf(aS[c4 + 3], av.w - bv.w, cS[c4 + 3])));
    }
}

__global__ void __launch_bounds__(256, 2)
k_l1(const int* __restrict__ gidx, const float* __restrict__ W1) {
    extern __shared__ __align__(16) float X[];   // [2][TM*LDS1]
    __shared__ float aS[C1], cS[C1];
    int tid = threadIdx.x;
    if (tid < C1) { aS[tid] = g_a0[tid]; cS[tid] = g_c0[tid]; }
    int w = tid >> 5, lane = tid & 31;
    int g = lane >> 2, t = lane & 3;
    int wm = w >> 2, wn = w & 3;
    // B-fragments cached in registers: B[k][n] = W1[n][k]
    uint32_t Bf[2][8][2];
    #pragma unroll
    for (int nf = 0; nf < 2; ++nf)
        #pragma unroll
        for (int kf = 0; kf < 8; ++kf) {
            int n = wn * 16 + nf * 8 + g;
            Bf[nf][kf][0] = __float_as_uint(tf32r(W1[n * C1 + kf * 8 + t]));
            Bf[nf][kf][1] = __float_as_uint(tf32r(W1[n * C1 + kf * 8 + t + 4]));
        }
    float sum[4] = {0, 0, 0, 0}, sq[4] = {0, 0, 0, 0};
    __syncthreads();

    int tile = blockIdx.x, buf = 0;
    stage1(X, tile, tid, gidx, aS, cS);
    for (; tile < NT1; tile += gridDim.x, buf ^= 1) {
        __syncthreads();
        int nxt = tile + gridDim.x;
        if (nxt < NT1) stage1(X + (buf ^ 1) * BUFSZ, nxt, tid, gidx, aS, cS);
        const float* Xb = X + buf * BUFSZ;
        #pragma unroll
        for (int mf = 0; mf < 4; ++mf) {
            int rb = wm * 64 + mf * 16;
            float ac0[4] = {0, 0, 0, 0}, ac1[4] = {0, 0, 0, 0};
            #pragma unroll
            for (int kf = 0; kf < 8; ++kf) {
                const float* p = Xb + (rb + g) * LDS1 + kf * 8 + t;
                uint32_t Af[4];
                Af[0] = __float_as_uint(p[0]);
                Af[1] = __float_as_uint(p[8 * LDS1]);
                Af[2] = __float_as_uint(p[4]);
                Af[3] = __float_as_uint(p[8 * LDS1 + 4]);
                mma8(ac0, Af, Bf[0][kf]);
                mma8(ac1, Af, Bf[1][kf]);
            }
            int srow = tile * TM + rb + g;
            int col0 = wn * 16 + 2 * t;
            *(float2*)&g_y1[(size_t)srow * C2 + col0]           = make_float2(ac0[0], ac0[1]);
            *(float2*)&g_y1[(size_t)(srow + 8) * C2 + col0]     = make_float2(ac0[2], ac0[3]);
            *(float2*)&g_y1[(size_t)srow * C2 + col0 + 8]       = make_float2(ac1[0], ac1[1]);
            *(float2*)&g_y1[(size_t)(srow + 8) * C2 + col0 + 8] = make_float2(ac1[2], ac1[3]);
            sum[0] += ac0[0] + ac0[2]; sq[0] += ac0[0] * ac0[0] + ac0[2] * ac0[2];
            sum[1] += ac0[1] + ac0[3]; sq[1] += ac0[1] * ac0[1] + ac0[3] * ac0[3];
            sum[2] += ac1[0] + ac1[2]; sq[2] += ac1[0] * ac1[0] + ac1[2] * ac1[2];
            sum[3] += ac1[1] + ac1[3]; sq[3] += ac1[1] * ac1[1] + ac1[3] * ac1[3];
        }
    }
    // reduce stats across lanes sharing t (xor 4,8,16), lanes g==0 commit
    #pragma unroll
    for (int sl = 0; sl < 4; ++sl) {
        float s = sum[sl], q = sq[sl];
        s += __shfl_xor_sync(~0u, s, 4);  q += __shfl_xor_sync(~0u, q, 4);
        s += __shfl_xor_sync(~0u, s, 8);  q += __shfl_xor_sync(~0u, q, 8);
        s += __shfl_xor_sync(~0u, s, 16); q += __shfl_xor_sync(~0u, q, 16);
        if (g == 0) {
            int col = wn * 16 + (sl >> 1) * 8 + 2 * t + (sl & 1);
            atomicAdd(&g_sum1[col], s);
            atomicAdd(&g_sq1[col], q);
        }
    }
}

// ---------------- layer2: y1 -> BN1+relu -> mma tf32 -> stats + pool -------
// 512 thr, 16 warps: wm = w>>3 (64 rows), wn = w&7 (16 cols). Bias b2 absorbed.
__device__ __forceinline__ void stage2(float* __restrict__ Xb, int tile, int tid,
                                       const float* aS, const float* cS) {
    #pragma unroll
    for (int i = 0; i < 4; ++i) {
        int idx = tid + i * 512;
        int r = idx >> 4, c4 = (idx & 15) * 4;
        float4 y = *(const float4*)&g_y1[(size_t)(tile * TM + r) * C2 + c4];
        float* row = Xb + r * LDS1;
        row[c4 + 0] = tf32r(fmaxf(0.f, fmaf(aS[c4 + 0], y.x, cS[c4 + 0])));
        row[c4 + 1] = tf32r(fmaxf(0.f, fmaf(aS[c4 + 1], y.y, cS[c4 + 1])));
        row[c4 + 2] = tf32r(fmaxf(0.f, fmaf(aS[c4 + 2], y.z, cS[c4 + 2])));
        row[c4 + 3] = tf32r(fmaxf(0.f, fmaf(aS[c4 + 3], y.w, cS[c4 + 3])));
    }
}

__global__ void __launch_bounds__(512, 1)
k_l2(const float* __restrict__ W2) {
    extern __shared__ __align__(16) float X[];   // [2][TM*LDS1]
    __shared__ float aS[C2], cS[C2];
    int tid = threadIdx.x;
    if (tid < C2) { aS[tid] = g_a1[tid]; cS[tid] = g_c1[tid]; }
    int w = tid >> 5, lane = tid & 31;
    int g = lane >> 2, t = lane & 3;
    int wm = w >> 3, wn = w & 7;
    uint32_t Bf[2][8][2];
    #pragma unroll
    for (int nf = 0; nf < 2; ++nf)
        #pragma unroll
        for (int kf = 0; kf < 8; ++kf) {
            int n = wn * 16 + nf * 8 + g;
            Bf[nf][kf][0] = __float_as_uint(tf32r(W2[n * C2 + kf * 8 + t]));
            Bf[nf][kf][1] = __float_as_uint(tf32r(W2[n * C2 + kf * 8 + t + 4]));
        }
    float sum[4] = {0, 0, 0, 0}, sq[4] = {0, 0, 0, 0};
    __syncthreads();

    int tile = blockIdx.x, buf = 0;
    stage2(X, tile, tid, aS, cS);
    for (; tile < NT1; tile += gridDim.x, buf ^= 1) {
        __syncthreads();
        int nxt = tile + gridDim.x;
        if (nxt < NT1) stage2(X + (buf ^ 1) * BUFSZ, nxt, tid, aS, cS);
        const float* Xb = X + buf * BUFSZ;
        float mxx[2][4], mnn[2][4];
        #pragma unroll
        for (int ps = 0; ps < 2; ++ps)
            #pragma unroll
            for (int sl = 0; sl < 4; ++sl) { mxx[ps][sl] = -1e30f; mnn[ps][sl] = 1e30f; }
        #pragma unroll
        for (int mf = 0; mf < 4; ++mf) {
            int rb = wm * 64 + mf * 16;
            float ac0[4] = {0, 0, 0, 0}, ac1[4] = {0, 0, 0, 0};
            #pragma unroll
            for (int kf = 0; kf < 8; ++kf) {
                const float* p = Xb + (rb + g) * LDS1 + kf * 8 + t;
                uint32_t Af[4];
                Af[0] = __float_as_uint(p[0]);
                Af[1] = __float_as_uint(p[8 * LDS1]);
                Af[2] = __float_as_uint(p[4]);
                Af[3] = __float_as_uint(p[8 * LDS1 + 4]);
                mma8(ac0, Af, Bf[0][kf]);
                mma8(ac1, Af, Bf[1][kf]);
            }
            int ps = mf >> 1;
            sum[0] += ac0[0] + ac0[2]; sq[0] += ac0[0] * ac0[0] + ac0[2] * ac0[2];
            sum[1] += ac0[1] + ac0[3]; sq[1] += ac0[1] * ac0[1] + ac0[3] * ac0[3];
            sum[2] += ac1[0] + ac1[2]; sq[2] += ac1[0] * ac1[0] + ac1[2] * ac1[2];
            sum[3] += ac1[1] + ac1[3]; sq[3] += ac1[1] * ac1[1] + ac1[3] * ac1[3];
            mxx[ps][0] = fmaxf(mxx[ps][0], fmaxf(ac0[0], ac0[2]));
            mxx[ps][1] = fmaxf(mxx[ps][1], fmaxf(ac0[1], ac0[3]));
            mxx[ps][2] = fmaxf(mxx[ps][2], fmaxf(ac1[0], ac1[2]));
            mxx[ps][3] = fmaxf(mxx[ps][3], fmaxf(ac1[1], ac1[3]));
            mnn[ps][0] = fminf(mnn[ps][0], fminf(ac0[0], ac0[2]));
            mnn[ps][1] = fminf(mnn[ps][1], fminf(ac0[1], ac0[3]));
            mnn[ps][2] = fminf(mnn[ps][2], fminf(ac1[0], ac1[2]));
            mnn[ps][3] = fminf(mnn[ps][3], fminf(ac1[1], ac1[3]));
        }
        // per-point per-column extrema: reduce across lanes sharing t
        #pragma unroll
        for (int ps = 0; ps < 2; ++ps)
            #pragma unroll
            for (int sl = 0; sl < 4; ++sl) {
                float mx = mxx[ps][sl], mn = mnn[ps][sl];
                mx = fmaxf(mx, __shfl_xor_sync(~0u, mx, 4));
                mn = fminf(mn, __shfl_xor_sync(~0u, mn, 4));
                mx = fmaxf(mx, __shfl_xor_sync(~0u, mx, 8));
                mn = fminf(mn, __shfl_xor_sync(~0u, mn, 8));
                mx = fmaxf(mx, __shfl_xor_sync(~0u, mx, 16));
                mn = fminf(mn, __shfl_xor_sync(~0u, mn, 16));
                if (g == 0) {
                    int col = wn * 16 + (sl >> 1) * 8 + 2 * t + (sl & 1);
                    int n = tile * 4 + wm * 2 + ps;
                    g_pmax[n * C3 + col] = mx;
                    g_pmin[n * C3 + col] = mn;
                }
            }
    }
    #pragma unroll
    for (int sl = 0; sl < 4; ++sl) {
        float s = sum[sl], q = sq[sl];
        s += __shfl_xor_sync(~0u, s, 4);  q += __shfl_xor_sync(~0u, q, 4);
        s += __shfl_xor_sync(~0u, s, 8);  q += __shfl_xor_sync(~0u, q, 8);
        s += __shfl_xor_sync(~0u, s, 16); q += __shfl_xor_sync(~0u, q, 16);
        if (g == 0) {
            int col = wn * 16 + (sl >> 1) * 8 + 2 * t + (sl & 1);
            atomicAdd(&g_sum2[col], s);
            atomicAdd(&g_sq2[col], q);
        }
    }
}

// ---------------- epilogue: BN2+relu on pooled extrema ---------------------
__global__ void k_poolapply(float* __restrict__ out) {
    int idx = blockIdx.x * blockDim.x + threadIdx.x;
    if (idx >= NPTS * (C3 / 4)) return;
    int n = idx >> 5, cg = (idx & 31) * 4;
    float4 a = *(const float4*)&g_a2[cg];
    float4 c = *(const float4*)&g_c2[cg];
    float4 mx = *(const float4*)&g_pmax[n * C3 + cg];
    float4 mn = *(const float4*)&g_pmin[n * C3 + cg];
    float4 o;
    o.x = fmaxf(0.f, fmaf(a.x, (a.x > 0.f) ? mx.x : mn.x, c.x));
    o.y = fmaxf(0.f, fmaf(a.y, (a.y > 0.f) ? mx.y : mn.y, c.y));
    o.z = fmaxf(0.f, fmaf(a.z, (a.z > 0.f) ? mx.z : mn.z, c.z));
    o.w = fmaxf(0.f, fmaf(a.w, (a.w > 0.f) ? mx.w : mn.w, c.w));
    *(float4*)&out[(size_t)n * C3 + cg] = o;
}

// ---------------- host entry ------------------------------------------------
extern "C" void kernel_launch(void* const* d_in, const int* in_sizes, int n_in,
                              void* d_out, int out_size) {
    const float* center  = (const float*)d_in[0];
    const float* normal  = (const float*)d_in[1];
    const float* feature = (const float*)d_in[2];
    const int*   offset  = (const int*)d_in[3];
    const int*   gidx    = (const int*)d_in[4];
    const float* W0 = (const float*)d_in[5];
    const float* b0 = (const float*)d_in[6];
    const float* g0 = (const float*)d_in[7];
    const float* be0 = (const float*)d_in[8];
    const float* W1 = (const float*)d_in[9];
    const float* g1 = (const float*)d_in[11];
    const float* be1 = (const float*)d_in[12];
    const float* W2 = (const float*)d_in[13];
    const float* g2 = (const float*)d_in[15];
    const float* be2 = (const float*)d_in[16];

    float* out = (float*)d_out;
    bool full = (out_size >= 2 * NPTS * 3 + NPTS * C3 + 1);
    float* featBase = full ? out + 2 * NPTS * 3 : out;

    const int SMX = 2 * BUFSZ * 4;   // 69632 B double-buffered staging
    cudaFuncSetAttribute(k_l1, cudaFuncAttributeMaxDynamicSharedMemorySize, SMX);
    cudaFuncSetAttribute(k_l2, cudaFuncAttributeMaxDynamicSharedMemorySize, SMX);

    k_zero<<<1, 128>>>();
    if (full) k_copy<<<256, 256>>>(center, normal, offset, out, 1);

    k_pre<<<160, BLK>>>(center, normal, feature, W0, b0);
    k_l0stats<<<1184, BLK>>>(gidx);
    k_fin0<<<1, 64>>>(g0, be0);
    k_l1<<<296, 256, SMX>>>(gidx, W1);
    k_fin1<<<1, 64>>>(g1, be1);
    k_l2<<<148, 512, SMX>>>(W2);
    k_fin2<<<1, 128>>>(g2, be2);
    k_poolapply<<<5000, BLK>>>(featBase);
}

// round 6
// speedup vs baseline: 2.2331x; 1.1735x over previous
#include <cuda_runtime.h>
#include <cuda_fp16.h>
#include <cstdint>

#define NPTS 40000
#define NSAMP 32
#define STOT (NPTS * NSAMP)     // 1,280,000
#define C0IN 38
#define C1 64
#define C2 64
#define C3 128
#define BNEPS 1e-5f
#define BLK 256
#define NWARP 8
#define TM 128
#define NT1 (STOT / TM)         // 10000 tiles
#define TILEH (TM * 64)         // halves per staging tile (16 KB)

// ---------------- scratch ---------------------------------------------------
__device__ __align__(16) float g_A[NPTS * C1];
__device__ __align__(16) float g_B[NPTS * C1];
__device__ __align__(16) __half2 g_y1h[(size_t)32 * STOT];   // [colpair][row], 164 MB
__device__ __align__(16) float g_pmax[NPTS * C3];
__device__ __align__(16) float g_pmin[NPTS * C3];

__device__ float g_sum0[C1], g_sq0[C1];
__device__ float g_sum1[C2], g_sq1[C2];
__device__ float g_sum2[C3], g_sq2[C3];
__device__ __align__(16) float g_a0[C1], g_c0[C1];
__device__ __align__(16) float g_a1[C2], g_c1[C2];
__device__ __align__(16) float g_a2[C3], g_c2[C3];

// ---------------- helpers ---------------------------------------------------
__device__ __forceinline__ void ldsm4(uint32_t* a, const __half* p) {
    uint32_t sa = (uint32_t)__cvta_generic_to_shared(p);
    asm volatile("ldmatrix.sync.aligned.m8n8.x4.shared.b16 {%0,%1,%2,%3}, [%4];"
                 : "=r"(a[0]), "=r"(a[1]), "=r"(a[2]), "=r"(a[3]) : "r"(sa));
}
__device__ __forceinline__ void mma16(float* d, const uint32_t* a, const uint32_t* b) {
    asm volatile(
        "mma.sync.aligned.m16n8k16.row.col.f32.f16.f16.f32 "
        "{%0,%1,%2,%3}, {%4,%5,%6,%7}, {%8,%9}, {%0,%1,%2,%3};"
        : "+f"(d[0]), "+f"(d[1]), "+f"(d[2]), "+f"(d[3])
        : "r"(a[0]), "r"(a[1]), "r"(a[2]), "r"(a[3]), "r"(b[0]), "r"(b[1]));
}
__device__ __forceinline__ uint32_t packh2(float x, float y) {
    __half2 h = __floats2half2_rn(x, y);
    return *reinterpret_cast<uint32_t*>(&h);
}

__global__ void k_zero() {
    int t = threadIdx.x;
    if (t < C1) { g_sum0[t] = 0.f; g_sq0[t] = 0.f; g_sum1[t] = 0.f; g_sq1[t] = 0.f; }
    if (t < C3) { g_sum2[t] = 0.f; g_sq2[t] = 0.f; }
}

__global__ void k_copy(const float* __restrict__ center,
                       const float* __restrict__ normal,
                       const int* __restrict__ offset,
                       float* __restrict__ out, int writeOffsetSlot) {
    int i = blockIdx.x * blockDim.x + threadIdx.x;
    int stride = gridDim.x * blockDim.x;
    for (; i < 2 * NPTS * 3; i += stride) {
        out[i] = (i < NPTS * 3) ? center[i] : normal[i - NPTS * 3];
    }
    if (writeOffsetSlot && blockIdx.x == 0 && threadIdx.x == 0) {
        out[2 * NPTS * 3 + NPTS * C3] = (float)offset[0];
    }
}

// ---------------- per-point precompute A = W0*x+b0, B = W0c*center ---------
__global__ void k_pre(const float* __restrict__ center,
                      const float* __restrict__ normal,
                      const float* __restrict__ feature,
                      const float* __restrict__ W0,
                      const float* __restrict__ b0) {
    __shared__ __align__(16) float Wt[C0IN * C1];
    __shared__ float xs[NWARP][C0IN];
    int tid = threadIdx.x;
    for (int i = tid; i < C0IN * C1; i += BLK) {
        int o = i / C0IN, c = i % C0IN;
        Wt[c * C1 + o] = W0[i];
    }
    __syncthreads();
    int w = tid >> 5, lane = tid & 31;
    int o0 = 2 * lane;
    float bias0 = b0[o0], bias1 = b0[o0 + 1];
    int wg = blockIdx.x * NWARP + w, nW = gridDim.x * NWARP;
    for (int n = wg; n < NPTS; n += nW) {
        {
            float v;
            if (lane < 3)      v = center[n * 3 + lane];
            else if (lane < 6) v = normal[n * 3 + lane - 3];
            else               v = feature[n * 32 + lane - 6];
            xs[w][lane] = v;
            if (lane < C0IN - 32) xs[w][32 + lane] = feature[n * 32 + 26 + lane];
        }
        __syncwarp();
        float a0 = 0.f, a1 = 0.f, bp0 = 0.f, bp1 = 0.f;
        #pragma unroll
        for (int c = 0; c < C0IN; ++c) {
            float2 wv = *(const float2*)&Wt[c * C1 + o0];
            float x = xs[w][c];
            a0 += wv.x * x; a1 += wv.y * x;
            if (c < 3) { bp0 += wv.x * x; bp1 += wv.y * x; }
        }
        *(float2*)&g_A[n * C1 + o0] = make_float2(a0 + bias0, a1 + bias1);
        *(float2*)&g_B[n * C1 + o0] = make_float2(bp0, bp1);
        __syncwarp();
    }
}

// ---------------- layer-0 stats: y0 = A[j]-B[n] ----------------------------
__global__ void k_l0stats(const int* __restrict__ gidx) {
    __shared__ float sS[C1], sQ[C1];
    int tid = threadIdx.x;
    if (tid < C1) { sS[tid] = 0.f; sQ[tid] = 0.f; }
    __syncthreads();
    int w = tid >> 5, lane = tid & 31, c0 = 2 * lane;
    float s0 = 0.f, s1 = 0.f, q0 = 0.f, q1 = 0.f;
    int wg = blockIdx.x * NWARP + w, nW = gridDim.x * NWARP;
    for (int n = wg; n < NPTS; n += nW) {
        float2 bv = *(const float2*)&g_B[n * C1 + c0];
        int js = gidx[n * NSAMP + lane];
        #pragma unroll
        for (int s = 0; s < NSAMP; ++s) {
            int j = __shfl_sync(0xffffffffu, js, s);
            float2 av = *(const float2*)&g_A[j * C1 + c0];
            float y0 = av.x - bv.x, y1v = av.y - bv.y;
            s0 += y0; s1 += y1v; q0 += y0 * y0; q1 += y1v * y1v;
        }
    }
    atomicAdd(&sS[c0], s0); atomicAdd(&sS[c0 + 1], s1);
    atomicAdd(&sQ[c0], q0); atomicAdd(&sQ[c0 + 1], q1);
    __syncthreads();
    if (tid < C1) { atomicAdd(&g_sum0[tid], sS[tid]); atomicAdd(&g_sq0[tid], sQ[tid]); }
}

__global__ void k_fin0(const float* __restrict__ g, const float* __restrict__ be) {
    int t = threadIdx.x;
    if (t < C1) {
        float inv = 1.f / (float)STOT;
        float mean = g_sum0[t] * inv;
        float var = g_sq0[t] * inv - mean * mean;
        float a = g[t] * rsqrtf(var + BNEPS);
        g_a0[t] = a;
        g_c0[t] = fmaf(-a, mean, be[t]);
    }
}
__global__ void k_fin1(const float* __restrict__ g, const float* __restrict__ be) {
    int t = threadIdx.x;
    if (t < C2) {
        float inv = 1.f / (float)STOT;
        float mean = g_sum1[t] * inv;
        float var = g_sq1[t] * inv - mean * mean;
        float a = g[t] * rsqrtf(var + BNEPS);
        g_a1[t] = a;
        g_c1[t] = fmaf(-a, mean, be[t]);
    }
}
__global__ void k_fin2(const float* __restrict__ g, const float* __restrict__ be) {
    int t = threadIdx.x;
    if (t < C3) {
        float inv = 1.f / (float)STOT;
        float mean = g_sum2[t] * inv;
        float var = g_sq2[t] * inv - mean * mean;
        float a = g[t] * rsqrtf(var + BNEPS);
        g_a2[t] = a;
        g_c2[t] = fmaf(-a, mean, be[t]);
    }
}

// ---------------- staging: gather + BN0 + relu -> fp16 swizzled tile -------
// XOR swizzle: 16B chunk c at row r lives at chunk (c ^ (r&7))
__device__ __forceinline__ void stage1(__half* __restrict__ Xb, int tile, int tid,
                                       const int* __restrict__ gidx,
                                       const float* aS, const float* cS) {
    int r = tid >> 1, hf = tid & 1;
    int s = tile * TM + r;
    int j = gidx[s];
    int n = s >> 5;
    const float* Aj = g_A + j * C1;
    const float* Bn = g_B + n * C1;
    #pragma unroll
    for (int cc = 0; cc < 4; ++cc) {
        int c16 = hf * 4 + cc;
        uint32_t pk[4];
        #pragma unroll
        for (int qq = 0; qq < 2; ++qq) {
            int c4 = c16 * 8 + qq * 4;
            float4 av = *(const float4*)(Aj + c4);
            float4 bv = *(const float4*)(Bn + c4);
            float x0 = fmaxf(0.f, fmaf(aS[c4 + 0], av.x - bv.x, cS[c4 + 0]));
            float x1 = fmaxf(0.f, fmaf(aS[c4 + 1], av.y - bv.y, cS[c4 + 1]));
            float x2 = fmaxf(0.f, fmaf(aS[c4 + 2], av.z - bv.z, cS[c4 + 2]));
            float x3 = fmaxf(0.f, fmaf(aS[c4 + 3], av.w - bv.w, cS[c4 + 3]));
            pk[qq * 2]     = packh2(x0, x1);
            pk[qq * 2 + 1] = packh2(x2, x3);
        }
        *(uint4*)(Xb + r * 64 + ((c16 ^ (r & 7)) << 3)) = make_uint4(pk[0], pk[1], pk[2], pk[3]);
    }
}

// ---------------- layer1: x1 -> fp16 mma -> y1h + stats --------------------
__global__ void __launch_bounds__(256, 3)
k_l1(const int* __restrict__ gidx, const float* __restrict__ W1) {
    extern __shared__ __align__(16) __half X[];   // [2][TILEH]
    __shared__ float aS[C1], cS[C1];
    int tid = threadIdx.x;
    if (tid < C1) { aS[tid] = g_a0[tid]; cS[tid] = g_c0[tid]; }
    int w = tid >> 5, lane = tid & 31;
    int g = lane >> 2, t = lane & 3;
    int wm = w >> 2, wn = w & 3;
    int sub = lane >> 3, ir = lane & 7;
    int rowoff = (sub & 1) * 8 + ir;
    int csel = sub >> 1;
    uint32_t Bf[2][4][2];
    #pragma unroll
    for (int nf = 0; nf < 2; ++nf)
        #pragma unroll
        for (int kf = 0; kf < 4; ++kf) {
            int n = wn * 16 + nf * 8 + g;
            const float* wr = W1 + n * C1 + kf * 16;
            Bf[nf][kf][0] = packh2(wr[2 * t], wr[2 * t + 1]);
            Bf[nf][kf][1] = packh2(wr[8 + 2 * t], wr[8 + 2 * t + 1]);
        }
    float sum[4] = {0, 0, 0, 0}, sq[4] = {0, 0, 0, 0};
    __syncthreads();

    int tile = blockIdx.x, buf = 0;
    stage1(X, tile, tid, gidx, aS, cS);
    for (; tile < NT1; tile += gridDim.x, buf ^= 1) {
        __syncthreads();
        int nxt = tile + gridDim.x;
        if (nxt < NT1) stage1(X + (buf ^ 1) * TILEH, nxt, tid, gidx, aS, cS);
        const __half* Xb = X + buf * TILEH;
        #pragma unroll
        for (int mf = 0; mf < 4; ++mf) {
            int rb = wm * 64 + mf * 16;
            float ac0[4] = {0, 0, 0, 0}, ac1[4] = {0, 0, 0, 0};
            #pragma unroll
            for (int kf = 0; kf < 4; ++kf) {
                uint32_t Af[4];
                ldsm4(Af, Xb + (rb + rowoff) * 64 + (((2 * kf + csel) ^ ir) << 3));
                mma16(ac0, Af, Bf[0][kf]);
                mma16(ac1, Af, Bf[1][kf]);
            }
            int srow = tile * TM + rb + g;
            int cp0 = wn * 8 + t, cp1 = cp0 + 4;
            g_y1h[(size_t)cp0 * STOT + srow]     = __floats2half2_rn(ac0[0], ac0[1]);
            g_y1h[(size_t)cp0 * STOT + srow + 8] = __floats2half2_rn(ac0[2], ac0[3]);
            g_y1h[(size_t)cp1 * STOT + srow]     = __floats2half2_rn(ac1[0], ac1[1]);
            g_y1h[(size_t)cp1 * STOT + srow + 8] = __floats2half2_rn(ac1[2], ac1[3]);
            sum[0] += ac0[0] + ac0[2]; sq[0] += ac0[0] * ac0[0] + ac0[2] * ac0[2];
            sum[1] += ac0[1] + ac0[3]; sq[1] += ac0[1] * ac0[1] + ac0[3] * ac0[3];
            sum[2] += ac1[0] + ac1[2]; sq[2] += ac1[0] * ac1[0] + ac1[2] * ac1[2];
            sum[3] += ac1[1] + ac1[3]; sq[3] += ac1[1] * ac1[1] + ac1[3] * ac1[3];
        }
    }
    #pragma unroll
    for (int sl = 0; sl < 4; ++sl) {
        float s = sum[sl], q = sq[sl];
        s += __shfl_xor_sync(~0u, s, 4);  q += __shfl_xor_sync(~0u, q, 4);
        s += __shfl_xor_sync(~0u, s, 8);  q += __shfl_xor_sync(~0u, q, 8);
        s += __shfl_xor_sync(~0u, s, 16); q += __shfl_xor_sync(~0u, q, 16);
        if (g == 0) {
            int col = wn * 16 + (sl >> 1) * 8 + 2 * t + (sl & 1);
            atomicAdd(&g_sum1[col], s);
            atomicAdd(&g_sq1[col], q);
        }
    }
}

// ---------------- staging for layer2: y1h -> BN1+relu -> fp16 tile ---------
__device__ __forceinline__ void stage2(__half* __restrict__ Xb, int tile, int tid,
                                       const float* aS, const float* cS) {
    int cp = tid & 31, rb2 = tid >> 5;   // 0..15
    size_t base = (size_t)cp * STOT + tile * TM + rb2 * 8;
    uint4 u0 = *(const uint4*)&g_y1h[base];
    uint4 u1 = *(const uint4*)&g_y1h[base + 4];
    float a0v = aS[2 * cp], c0v = cS[2 * cp];
    float a1v = aS[2 * cp + 1], c1v = cS[2 * cp + 1];
    int c16 = cp >> 2, off = (cp & 3) * 2;
    uint32_t us[8] = {u0.x, u0.y, u0.z, u0.w, u1.x, u1.y, u1.z, u1.w};
    #pragma unroll
    for (int i = 0; i < 8; ++i) {
        int r = rb2 * 8 + i;
        __half2 hv = *reinterpret_cast<__half2*>(&us[i]);
        float2 f = __half22float2(hv);
        float x0 = fmaxf(0.f, fmaf(a0v, f.x, c0v));
        float x1 = fmaxf(0.f, fmaf(a1v, f.y, c1v));
        uint32_t ho = packh2(x0, x1);
        *(uint32_t*)(Xb + r * 64 + (((c16) ^ (r & 7)) << 3) + off) = ho;
    }
}

// ---------------- layer2: x2 -> fp16 mma -> stats + pool -------------------
__global__ void __launch_bounds__(512)
k_l2(const float* __restrict__ W2) {
    extern __shared__ __align__(16) __half X[];   // [2][TILEH]
    __shared__ float aS[C2], cS[C2];
    int tid = threadIdx.x;
    if (tid < C2) { aS[tid] = g_a1[tid]; cS[tid] = g_c1[tid]; }
    int w = tid >> 5, lane = tid & 31;
    int g = lane >> 2, t = lane & 3;
    int wm = w >> 3, wn = w & 7;
    int sub = lane >> 3, ir = lane & 7;
    int rowoff = (sub & 1) * 8 + ir;
    int csel = sub >> 1;
    uint32_t Bf[2][4][2];
    #pragma unroll
    for (int nf = 0; nf < 2; ++nf)
        #pragma unroll
        for (int kf = 0; kf < 4; ++kf) {
            int n = wn * 16 + nf * 8 + g;
            const float* wr = W2 + n * C2 + kf * 16;
            Bf[nf][kf][0] = packh2(wr[2 * t], wr[2 * t + 1]);
            Bf[nf][kf][1] = packh2(wr[8 + 2 * t], wr[8 + 2 * t + 1]);
        }
    float sum[4] = {0, 0, 0, 0}, sq[4] = {0, 0, 0, 0};
    __syncthreads();

    int tile = blockIdx.x, buf = 0;
    stage2(X, tile, tid, aS, cS);
    for (; tile < NT1; tile += gridDim.x, buf ^= 1) {
        __syncthreads();
        int nxt = tile + gridDim.x;
        if (nxt < NT1) stage2(X + (buf ^ 1) * TILEH, nxt, tid, aS, cS);
        const __half* Xb = X + buf * TILEH;
        float mxx[2][4], mnn[2][4];
        #pragma unroll
        for (int ps = 0; ps < 2; ++ps)
            #pragma unroll
            for (int sl = 0; sl < 4; ++sl) { mxx[ps][sl] = -1e30f; mnn[ps][sl] = 1e30f; }
        #pragma unroll
        for (int mf = 0; mf < 4; ++mf) {
            int rb = wm * 64 + mf * 16;
            float ac0[4] = {0, 0, 0, 0}, ac1[4] = {0, 0, 0, 0};
            #pragma unroll
            for (int kf = 0; kf < 4; ++kf) {
                uint32_t Af[4];
                ldsm4(Af, Xb + (rb + rowoff) * 64 + (((2 * kf + csel) ^ ir) << 3));
                mma16(ac0, Af, Bf[0][kf]);
                mma16(ac1, Af, Bf[1][kf]);
            }
            int ps = mf >> 1;
            sum[0] += ac0[0] + ac0[2]; sq[0] += ac0[0] * ac0[0] + ac0[2] * ac0[2];
            sum[1] += ac0[1] + ac0[3]; sq[1] += ac0[1] * ac0[1] + ac0[3] * ac0[3];
            sum[2] += ac1[0] + ac1[2]; sq[2] += ac1[0] * ac1[0] + ac1[2] * ac1[2];
            sum[3] += ac1[1] + ac1[3]; sq[3] += ac1[1] * ac1[1] + ac1[3] * ac1[3];
            mxx[ps][0] = fmaxf(mxx[ps][0], fmaxf(ac0[0], ac0[2]));
            mxx[ps][1] = fmaxf(mxx[ps][1], fmaxf(ac0[1], ac0[3]));
            mxx[ps][2] = fmaxf(mxx[ps][2], fmaxf(ac1[0], ac1[2]));
            mxx[ps][3] = fmaxf(mxx[ps][3], fmaxf(ac1[1], ac1[3]));
            mnn[ps][0] = fminf(mnn[ps][0], fminf(ac0[0], ac0[2]));
            mnn[ps][1] = fminf(mnn[ps][1], fminf(ac0[1], ac0[3]));
            mnn[ps][2] = fminf(mnn[ps][2], fminf(ac1[0], ac1[2]));
            mnn[ps][3] = fminf(mnn[ps][3], fminf(ac1[1], ac1[3]));
        }
        #pragma unroll
        for (int ps = 0; ps < 2; ++ps)
            #pragma unroll
            for (int sl = 0; sl < 4; ++sl) {
                float mx = mxx[ps][sl], mn = mnn[ps][sl];
                mx = fmaxf(mx, __shfl_xor_sync(~0u, mx, 4));
                mn = fminf(mn, __shfl_xor_sync(~0u, mn, 4));
                mx = fmaxf(mx, __shfl_xor_sync(~0u, mx, 8));
                mn = fminf(mn, __shfl_xor_sync(~0u, mn, 8));
                mx = fmaxf(mx, __shfl_xor_sync(~0u, mx, 16));
                mn = fminf(mn, __shfl_xor_sync(~0u, mn, 16));
                if (g == 0) {
                    int col = wn * 16 + (sl >> 1) * 8 + 2 * t + (sl & 1);
                    int n = tile * 4 + wm * 2 + ps;
                    g_pmax[n * C3 + col] = mx;
                    g_pmin[n * C3 + col] = mn;
                }
            }
    }
    #pragma unroll
    for (int sl = 0; sl < 4; ++sl) {
        float s = sum[sl], q = sq[sl];
        s += __shfl_xor_sync(~0u, s, 4);  q += __shfl_xor_sync(~0u, q, 4);
        s += __shfl_xor_sync(~0u, s, 8);  q += __shfl_xor_sync(~0u, q, 8);
        s += __shfl_xor_sync(~0u, s, 16); q += __shfl_xor_sync(~0u, q, 16);
        if (g == 0) {
            int col = wn * 16 + (sl >> 1) * 8 + 2 * t + (sl & 1);
            atomicAdd(&g_sum2[col], s);
            atomicAdd(&g_sq2[col], q);
        }
    }
}

// ---------------- epilogue: BN2+relu on pooled extrema ---------------------
__global__ void k_poolapply(float* __restrict__ out) {
    int idx = blockIdx.x * blockDim.x + threadIdx.x;
    if (idx >= NPTS * (C3 / 4)) return;
    int n = idx >> 5, cg = (idx & 31) * 4;
    float4 a = *(const float4*)&g_a2[cg];
    float4 c = *(const float4*)&g_c2[cg];
    float4 mx = *(const float4*)&g_pmax[n * C3 + cg];
    float4 mn = *(const float4*)&g_pmin[n * C3 + cg];
    float4 o;
    o.x = fmaxf(0.f, fmaf(a.x, (a.x > 0.f) ? mx.x : mn.x, c.x));
    o.y = fmaxf(0.f, fmaf(a.y, (a.y > 0.f) ? mx.y : mn.y, c.y));
    o.z = fmaxf(0.f, fmaf(a.z, (a.z > 0.f) ? mx.z : mn.z, c.z));
    o.w = fmaxf(0.f, fmaf(a.w, (a.w > 0.f) ? mx.w : mn.w, c.w));
    *(float4*)&out[(size_t)n * C3 + cg] = o;
}

// ---------------- host entry ------------------------------------------------
extern "C" void kernel_launch(void* const* d_in, const int* in_sizes, int n_in,
                              void* d_out, int out_size) {
    const float* center  = (const float*)d_in[0];
    const float* normal  = (const float*)d_in[1];
    const float* feature = (const float*)d_in[2];
    const int*   offset  = (const int*)d_in[3];
    const int*   gidx    = (const int*)d_in[4];
    const float* W0 = (const float*)d_in[5];
    const float* b0 = (const float*)d_in[6];
    const float* g0 = (const float*)d_in[7];
    const float* be0 = (const float*)d_in[8];
    const float* W1 = (const float*)d_in[9];
    const float* g1 = (const float*)d_in[11];
    const float* be1 = (const float*)d_in[12];
    const float* W2 = (const float*)d_in[13];
    const float* g2 = (const float*)d_in[15];
    const float* be2 = (const float*)d_in[16];

    float* out = (float*)d_out;
    bool full = (out_size >= 2 * NPTS * 3 + NPTS * C3 + 1);
    float* featBase = full ? out + 2 * NPTS * 3 : out;

    const int SMX = 2 * TILEH * 2;   // 32768 B double-buffered fp16 staging

    k_zero<<<1, 128>>>();
    if (full) k_copy<<<256, 256>>>(center, normal, offset, out, 1);

    k_pre<<<160, BLK>>>(center, normal, feature, W0, b0);
    k_l0stats<<<1184, BLK>>>(gidx);
    k_fin0<<<1, 64>>>(g0, be0);
    k_l1<<<444, 256, SMX>>>(gidx, W1);
    k_fin1<<<1, 64>>>(g1, be1);
    k_l2<<<148, 512, SMX>>>(W2);
    k_fin2<<<1, 128>>>(g2, be2);
    k_poolapply<<<5000, BLK>>>(featBase);
}

// round 7
// speedup vs baseline: 3.2465x; 1.4538x over previous
#include <cuda_runtime.h>
#include <cuda_fp16.h>
#include <cstdint>

#define NPTS 40000
#define NSAMP 32
#define STOT (NPTS * NSAMP)     // 1,280,000
#define C0IN 38
#define C1 64
#define C2 64
#define C3 128
#define BNEPS 1e-5f
#define BLK 256
#define NWARP 8
#define TM 128
#define NT1 (STOT / TM)         // 10000 tiles
#define TILEH (TM * 64)         // halves per staging tile (16 KB)

// ---------------- scratch ---------------------------------------------------
__device__ __align__(16) float g_A[NPTS * C1];
__device__ __align__(16) float g_B[NPTS * C1];
__device__ __align__(16) uint4 g_y1f[(size_t)NT1 * 1024];   // fragment-linear fp16 y1, 164 MB
__device__ __align__(16) float g_pmax[NPTS * C3];
__device__ __align__(16) float g_pmin[NPTS * C3];

__device__ float g_sum0[C1], g_sq0[C1];
__device__ float g_sum1[C2], g_sq1[C2];
__device__ float g_sum2[C3], g_sq2[C3];
__device__ __align__(16) float g_a0[C1], g_c0[C1];
__device__ __align__(16) float g_a1[C2], g_c1[C2];
__device__ __align__(16) float g_a2[C3], g_c2[C3];

// ---------------- helpers ---------------------------------------------------
__device__ __forceinline__ void ldsm4(uint32_t* a, const __half* p) {
    uint32_t sa = (uint32_t)__cvta_generic_to_shared(p);
    asm volatile("ldmatrix.sync.aligned.m8n8.x4.shared.b16 {%0,%1,%2,%3}, [%4];"
                 : "=r"(a[0]), "=r"(a[1]), "=r"(a[2]), "=r"(a[3]) : "r"(sa));
}
__device__ __forceinline__ void mma16(float* d, const uint32_t* a, const uint32_t* b) {
    asm volatile(
        "mma.sync.aligned.m16n8k16.row.col.f32.f16.f16.f32 "
        "{%0,%1,%2,%3}, {%4,%5,%6,%7}, {%8,%9}, {%0,%1,%2,%3};"
        : "+f"(d[0]), "+f"(d[1]), "+f"(d[2]), "+f"(d[3])
        : "r"(a[0]), "r"(a[1]), "r"(a[2]), "r"(a[3]), "r"(b[0]), "r"(b[1]));
}
__device__ __forceinline__ uint32_t packh2(float x, float y) {
    __half2 h = __floats2half2_rn(x, y);
    return *reinterpret_cast<uint32_t*>(&h);
}

__global__ void k_zero() {
    int t = threadIdx.x;
    if (t < C1) { g_sum0[t] = 0.f; g_sq0[t] = 0.f; g_sum1[t] = 0.f; g_sq1[t] = 0.f; }
    if (t < C3) { g_sum2[t] = 0.f; g_sq2[t] = 0.f; }
}

__global__ void k_copy(const float* __restrict__ center,
                       const float* __restrict__ normal,
                       const int* __restrict__ offset,
                       float* __restrict__ out, int writeOffsetSlot) {
    int i = blockIdx.x * blockDim.x + threadIdx.x;
    int stride = gridDim.x * blockDim.x;
    for (; i < 2 * NPTS * 3; i += stride) {
        out[i] = (i < NPTS * 3) ? center[i] : normal[i - NPTS * 3];
    }
    if (writeOffsetSlot && blockIdx.x == 0 && threadIdx.x == 0) {
        out[2 * NPTS * 3 + NPTS * C3] = (float)offset[0];
    }
}

// ---------------- per-point precompute A = W0*x+b0, B = W0c*center ---------
__global__ void k_pre(const float* __restrict__ center,
                      const float* __restrict__ normal,
                      const float* __restrict__ feature,
                      const float* __restrict__ W0,
                      const float* __restrict__ b0) {
    __shared__ __align__(16) float Wt[C0IN * C1];
    __shared__ float xs[NWARP][C0IN];
    int tid = threadIdx.x;
    for (int i = tid; i < C0IN * C1; i += BLK) {
        int o = i / C0IN, c = i % C0IN;
        Wt[c * C1 + o] = W0[i];
    }
    __syncthreads();
    int w = tid >> 5, lane = tid & 31;
    int o0 = 2 * lane;
    float bias0 = b0[o0], bias1 = b0[o0 + 1];
    int wg = blockIdx.x * NWARP + w, nW = gridDim.x * NWARP;
    for (int n = wg; n < NPTS; n += nW) {
        {
            float v;
            if (lane < 3)      v = center[n * 3 + lane];
            else if (lane < 6) v = normal[n * 3 + lane - 3];
            else               v = feature[n * 32 + lane - 6];
            xs[w][lane] = v;
            if (lane < C0IN - 32) xs[w][32 + lane] = feature[n * 32 + 26 + lane];
        }
        __syncwarp();
        float a0 = 0.f, a1 = 0.f, bp0 = 0.f, bp1 = 0.f;
        #pragma unroll
        for (int c = 0; c < C0IN; ++c) {
            float2 wv = *(const float2*)&Wt[c * C1 + o0];
            float x = xs[w][c];
            a0 += wv.x * x; a1 += wv.y * x;
            if (c < 3) { bp0 += wv.x * x; bp1 += wv.y * x; }
        }
        *(float2*)&g_A[n * C1 + o0] = make_float2(a0 + bias0, a1 + bias1);
        *(float2*)&g_B[n * C1 + o0] = make_float2(bp0, bp1);
        __syncwarp();
    }
}

// ---------------- layer-0 stats: y0 = A[j]-B[n] ----------------------------
__global__ void k_l0stats(const int* __restrict__ gidx) {
    __shared__ float sS[C1], sQ[C1];
    int tid = threadIdx.x;
    if (tid < C1) { sS[tid] = 0.f; sQ[tid] = 0.f; }
    __syncthreads();
    int w = tid >> 5, lane = tid & 31, c0 = 2 * lane;
    float s0 = 0.f, s1 = 0.f, q0 = 0.f, q1 = 0.f;
    int wg = blockIdx.x * NWARP + w, nW = gridDim.x * NWARP;
    for (int n = wg; n < NPTS; n += nW) {
        float2 bv = *(const float2*)&g_B[n * C1 + c0];
        int js = gidx[n * NSAMP + lane];
        #pragma unroll
        for (int s = 0; s < NSAMP; ++s) {
            int j = __shfl_sync(0xffffffffu, js, s);
            float2 av = *(const float2*)&g_A[j * C1 + c0];
            float y0 = av.x - bv.x, y1v = av.y - bv.y;
            s0 += y0; s1 += y1v; q0 += y0 * y0; q1 += y1v * y1v;
        }
    }
    atomicAdd(&sS[c0], s0); atomicAdd(&sS[c0 + 1], s1);
    atomicAdd(&sQ[c0], q0); atomicAdd(&sQ[c0 + 1], q1);
    __syncthreads();
    if (tid < C1) { atomicAdd(&g_sum0[tid], sS[tid]); atomicAdd(&g_sq0[tid], sQ[tid]); }
}

__global__ void k_fin0(const float* __restrict__ g, const float* __restrict__ be) {
    int t = threadIdx.x;
    if (t < C1) {
        float inv = 1.f / (float)STOT;
        float mean = g_sum0[t] * inv;
        float var = g_sq0[t] * inv - mean * mean;
        float a = g[t] * rsqrtf(var + BNEPS);
        g_a0[t] = a;
        g_c0[t] = fmaf(-a, mean, be[t]);
    }
}
__global__ void k_fin1(const float* __restrict__ g, const float* __restrict__ be) {
    int t = threadIdx.x;
    if (t < C2) {
        float inv = 1.f / (float)STOT;
        float mean = g_sum1[t] * inv;
        float var = g_sq1[t] * inv - mean * mean;
        float a = g[t] * rsqrtf(var + BNEPS);
        g_a1[t] = a;
        g_c1[t] = fmaf(-a, mean, be[t]);
    }
}
__global__ void k_fin2(const float* __restrict__ g, const float* __restrict__ be) {
    int t = threadIdx.x;
    if (t < C3) {
        float inv = 1.f / (float)STOT;
        float mean = g_sum2[t] * inv;
        float var = g_sq2[t] * inv - mean * mean;
        float a = g[t] * rsqrtf(var + BNEPS);
        g_a2[t] = a;
        g_c2[t] = fmaf(-a, mean, be[t]);
    }
}

// ---------------- coalesced gather staging ---------------------------------
// lane = (hw, ch): ch = lane&15 -> 16B chunk of the 256B row; hw = row of pair.
// One LDG.128 covers 2 complete A rows -> 4 lines/inst. B row shared per warp.
__device__ __forceinline__ void stage1(__half* __restrict__ Xb, int tile, int w, int lane,
                                       const int* __restrict__ gidx,
                                       float4 a4, float4 c4) {
    int ch = lane & 15, hw = lane >> 4;
    int jreg = gidx[tile * TM + w * 16 + ch];
    int n = tile * 4 + (w >> 1);
    float4 bv = *(const float4*)&g_B[n * C1 + ch * 4];
    #pragma unroll
    for (int i = 0; i < 8; ++i) {
        int r = w * 16 + i * 2 + hw;
        int j = __shfl_sync(0xffffffffu, jreg, i * 2 + hw);
        float4 av = *(const float4*)&g_A[(size_t)j * C1 + ch * 4];
        float x0 = fmaxf(0.f, fmaf(a4.x, av.x - bv.x, c4.x));
        float x1 = fmaxf(0.f, fmaf(a4.y, av.y - bv.y, c4.y));
        float x2 = fmaxf(0.f, fmaf(a4.z, av.z - bv.z, c4.z));
        float x3 = fmaxf(0.f, fmaf(a4.w, av.w - bv.w, c4.w));
        uint32_t u0 = packh2(x0, x1), u1 = packh2(x2, x3);
        *(uint2*)(Xb + r * 64 + (((ch >> 1) ^ (r & 7)) << 3) + (ch & 1) * 4) = make_uint2(u0, u1);
    }
}

// ---------------- layer1: x1 -> fp16 mma -> y1f (coalesced) + stats --------
__global__ void __launch_bounds__(256, 3)
k_l1(const int* __restrict__ gidx, const float* __restrict__ W1) {
    extern __shared__ __align__(16) __half X[];   // [2][TILEH]
    __shared__ float aS[C1], cS[C1];
    int tid = threadIdx.x;
    if (tid < C1) { aS[tid] = g_a0[tid]; cS[tid] = g_c0[tid]; }
    int w = tid >> 5, lane = tid & 31;
    int g = lane >> 2, t = lane & 3;
    int wm = w >> 2, wn = w & 3;
    int sub = lane >> 3, ir = lane & 7;
    int rowoff = (sub & 1) * 8 + ir;
    int csel = sub >> 1;
    uint32_t Bf[2][4][2];
    #pragma unroll
    for (int nf = 0; nf < 2; ++nf)
        #pragma unroll
        for (int kf = 0; kf < 4; ++kf) {
            int n = wn * 16 + nf * 8 + g;
            const float* wr = W1 + n * C1 + kf * 16;
            Bf[nf][kf][0] = packh2(wr[2 * t], wr[2 * t + 1]);
            Bf[nf][kf][1] = packh2(wr[8 + 2 * t], wr[8 + 2 * t + 1]);
        }
    float sum[4] = {0, 0, 0, 0}, sq[4] = {0, 0, 0, 0};
    __syncthreads();
    int ch = lane & 15;
    float4 a4 = *(const float4*)&aS[ch * 4];
    float4 c4 = *(const float4*)&cS[ch * 4];

    int tile = blockIdx.x, buf = 0;
    stage1(X, tile, w, lane, gidx, a4, c4);
    for (; tile < NT1; tile += gridDim.x, buf ^= 1) {
        __syncthreads();
        int nxt = tile + gridDim.x;
        if (nxt < NT1) stage1(X + (buf ^ 1) * TILEH, nxt, w, lane, gidx, a4, c4);
        const __half* Xb = X + buf * TILEH;
        #pragma unroll
        for (int mf = 0; mf < 4; ++mf) {
            int rb = wm * 64 + mf * 16;
            float ac0[4] = {0, 0, 0, 0}, ac1[4] = {0, 0, 0, 0};
            #pragma unroll
            for (int kf = 0; kf < 4; ++kf) {
                uint32_t Af[4];
                ldsm4(Af, Xb + (rb + rowoff) * 64 + (((2 * kf + csel) ^ ir) << 3));
                mma16(ac0, Af, Bf[0][kf]);
                mma16(ac1, Af, Bf[1][kf]);
            }
            uint4 pv;
            pv.x = packh2(ac0[0], ac0[1]);
            pv.y = packh2(ac0[2], ac0[3]);
            pv.z = packh2(ac1[0], ac1[1]);
            pv.w = packh2(ac1[2], ac1[3]);
            g_y1f[(size_t)tile * 1024 + w * 128 + mf * 32 + lane] = pv;
            sum[0] += ac0[0] + ac0[2]; sq[0] += ac0[0] * ac0[0] + ac0[2] * ac0[2];
            sum[1] += ac0[1] + ac0[3]; sq[1] += ac0[1] * ac0[1] + ac0[3] * ac0[3];
            sum[2] += ac1[0] + ac1[2]; sq[2] += ac1[0] * ac1[0] + ac1[2] * ac1[2];
            sum[3] += ac1[1] + ac1[3]; sq[3] += ac1[1] * ac1[1] + ac1[3] * ac1[3];
        }
    }
    #pragma unroll
    for (int sl = 0; sl < 4; ++sl) {
        float s = sum[sl], q = sq[sl];
        s += __shfl_xor_sync(~0u, s, 4);  q += __shfl_xor_sync(~0u, q, 4);
        s += __shfl_xor_sync(~0u, s, 8);  q += __shfl_xor_sync(~0u, q, 8);
        s += __shfl_xor_sync(~0u, s, 16); q += __shfl_xor_sync(~0u, q, 16);
        if (g == 0) {
            int col = wn * 16 + (sl >> 1) * 8 + 2 * t + (sl & 1);
            atomicAdd(&g_sum1[col], s);
            atomicAdd(&g_sq1[col], q);
        }
    }
}

// ---------------- layer2 staging: y1f (coalesced LDG) -> BN1+relu -> tile --
__device__ __forceinline__ void stage2(__half* __restrict__ Xb, int tile, int tid,
                                       const float* aS, const float* cS) {
    #pragma unroll
    for (int it = 0; it < 2; ++it) {
        int u = tid + it * 512;
        int w1 = u >> 7, mf = (u >> 5) & 3, ln = u & 31;
        int gg = ln >> 2, tt = ln & 3;
        int rb = (w1 >> 2) * 64 + mf * 16;
        int r0 = rb + gg, r1 = rb + gg + 8;
        int wn1 = w1 & 3;
        int cp0 = wn1 * 8 + tt, cp1 = cp0 + 4;
        uint4 v = g_y1f[(size_t)tile * 1024 + u];
        float2 a0v = *(const float2*)&aS[2 * cp0], c0v = *(const float2*)&cS[2 * cp0];
        float2 a1v = *(const float2*)&aS[2 * cp1], c1v = *(const float2*)&cS[2 * cp1];
        float2 f;
        f = __half22float2(*(__half2*)&v.x);
        uint32_t u00 = packh2(fmaxf(0.f, fmaf(a0v.x, f.x, c0v.x)),
                              fmaxf(0.f, fmaf(a0v.y, f.y, c0v.y)));
        f = __half22float2(*(__half2*)&v.y);
        uint32_t u01 = packh2(fmaxf(0.f, fmaf(a0v.x, f.x, c0v.x)),
                              fmaxf(0.f, fmaf(a0v.y, f.y, c0v.y)));
        f = __half22float2(*(__half2*)&v.z);
        uint32_t u10 = packh2(fmaxf(0.f, fmaf(a1v.x, f.x, c1v.x)),
                              fmaxf(0.f, fmaf(a1v.y, f.y, c1v.y)));
        f = __half22float2(*(__half2*)&v.w);
        uint32_t u11 = packh2(fmaxf(0.f, fmaf(a1v.x, f.x, c1v.x)),
                              fmaxf(0.f, fmaf(a1v.y, f.y, c1v.y)));
        int ch0 = 2 * wn1, ch1 = 2 * wn1 + 1;
        *(uint32_t*)(Xb + r0 * 64 + ((ch0 ^ (r0 & 7)) << 3) + tt * 2) = u00;
        *(uint32_t*)(Xb + r1 * 64 + ((ch0 ^ (r1 & 7)) << 3) + tt * 2) = u01;
        *(uint32_t*)(Xb + r0 * 64 + ((ch1 ^ (r0 & 7)) << 3) + tt * 2) = u10;
        *(uint32_t*)(Xb + r1 * 64 + ((ch1 ^ (r1 & 7)) << 3) + tt * 2) = u11;
    }
}

// ---------------- layer2: x2 -> fp16 mma -> stats + pool -------------------
__global__ void __launch_bounds__(512)
k_l2(const float* __restrict__ W2) {
    extern __shared__ __align__(16) __half X[];   // [2][TILEH]
    __shared__ float aS[C2], cS[C2];
    int tid = threadIdx.x;
    if (tid < C2) { aS[tid] = g_a1[tid]; cS[tid] = g_c1[tid]; }
    int w = tid >> 5, lane = tid & 31;
    int g = lane >> 2, t = lane & 3;
    int wm = w >> 3, wn = w & 7;
    int sub = lane >> 3, ir = lane & 7;
    int rowoff = (sub & 1) * 8 + ir;
    int csel = sub >> 1;
    uint32_t Bf[2][4][2];
    #pragma unroll
    for (int nf = 0; nf < 2; ++nf)
        #pragma unroll
        for (int kf = 0; kf < 4; ++kf) {
            int n = wn * 16 + nf * 8 + g;
            const float* wr = W2 + n * C2 + kf * 16;
            Bf[nf][kf][0] = packh2(wr[2 * t], wr[2 * t + 1]);
            Bf[nf][kf][1] = packh2(wr[8 + 2 * t], wr[8 + 2 * t + 1]);
        }
    float sum[4] = {0, 0, 0, 0}, sq[4] = {0, 0, 0, 0};
    __syncthreads();

    int tile = blockIdx.x, buf = 0;
    stage2(X, tile, tid, aS, cS);
    for (; tile < NT1; tile += gridDim.x, buf ^= 1) {
        __syncthreads();
        int nxt = tile + gridDim.x;
        if (nxt < NT1) stage2(X + (buf ^ 1) * TILEH, nxt, tid, aS, cS);
        const __half* Xb = X + buf * TILEH;
        float mxx[2][4], mnn[2][4];
        #pragma unroll
        for (int ps = 0; ps < 2; ++ps)
            #pragma unroll
            for (int sl = 0; sl < 4; ++sl) { mxx[ps][sl] = -1e30f; mnn[ps][sl] = 1e30f; }
        #pragma unroll
        for (int mf = 0; mf < 4; ++mf) {
            int rb = wm * 64 + mf * 16;
            float ac0[4] = {0, 0, 0, 0}, ac1[4] = {0, 0, 0, 0};
            #pragma unroll
            for (int kf = 0; kf < 4; ++kf) {
                uint32_t Af[4];
                ldsm4(Af, Xb + (rb + rowoff) * 64 + (((2 * kf + csel) ^ ir) << 3));
                mma16(ac0, Af, Bf[0][kf]);
                mma16(ac1, Af, Bf[1][kf]);
            }
            int ps = mf >> 1;
            sum[0] += ac0[0] + ac0[2]; sq[0] += ac0[0] * ac0[0] + ac0[2] * ac0[2];
            sum[1] += ac0[1] + ac0[3]; sq[1] += ac0[1] * ac0[1] + ac0[3] * ac0[3];
            sum[2] += ac1[0] + ac1[2]; sq[2] += ac1[0] * ac1[0] + ac1[2] * ac1[2];
            sum[3] += ac1[1] + ac1[3]; sq[3] += ac1[1] * ac1[1] + ac1[3] * ac1[3];
            mxx[ps][0] = fmaxf(mxx[ps][0], fmaxf(ac0[0], ac0[2]));
            mxx[ps][1] = fmaxf(mxx[ps][1], fmaxf(ac0[1], ac0[3]));
            mxx[ps][2] = fmaxf(mxx[ps][2], fmaxf(ac1[0], ac1[2]));
            mxx[ps][3] = fmaxf(mxx[ps][3], fmaxf(ac1[1], ac1[3]));
            mnn[ps][0] = fminf(mnn[ps][0], fminf(ac0[0], ac0[2]));
            mnn[ps][1] = fminf(mnn[ps][1], fminf(ac0[1], ac0[3]));
            mnn[ps][2] = fminf(mnn[ps][2], fminf(ac1[0], ac1[2]));
            mnn[ps][3] = fminf(mnn[ps][3], fminf(ac1[1], ac1[3]));
        }
        #pragma unroll
        for (int ps = 0; ps < 2; ++ps)
            #pragma unroll
            for (int sl = 0; sl < 4; ++sl) {
                float mx = mxx[ps][sl], mn = mnn[ps][sl];
                mx = fmaxf(mx, __shfl_xor_sync(~0u, mx, 4));
                mn = fminf(mn, __shfl_xor_sync(~0u, mn, 4));
                mx = fmaxf(mx, __shfl_xor_sync(~0u, mx, 8));
                mn = fminf(mn, __shfl_xor_sync(~0u, mn, 8));
                mx = fmaxf(mx, __shfl_xor_sync(~0u, mx, 16));
                mn = fminf(mn, __shfl_xor_sync(~0u, mn, 16));
                if (g == 0) {
                    int col = wn * 16 + (sl >> 1) * 8 + 2 * t + (sl & 1);
                    int n = tile * 4 + wm * 2 + ps;
                    g_pmax[n * C3 + col] = mx;
                    g_pmin[n * C3 + col] = mn;
                }
            }
    }
    #pragma unroll
    for (int sl = 0; sl < 4; ++sl) {
        float s = sum[sl], q = sq[sl];
        s += __shfl_xor_sync(~0u, s, 4);  q += __shfl_xor_sync(~0u, q, 4);
        s += __shfl_xor_sync(~0u, s, 8);  q += __shfl_xor_sync(~0u, q, 8);
        s += __shfl_xor_sync(~0u, s, 16); q += __shfl_xor_sync(~0u, q, 16);
        if (g == 0) {
            int col = wn * 16 + (sl >> 1) * 8 + 2 * t + (sl & 1);
            atomicAdd(&g_sum2[col], s);
            atomicAdd(&g_sq2[col], q);
        }
    }
}

// ---------------- epilogue: BN2+relu on pooled extrema ---------------------
__global__ void k_poolapply(float* __restrict__ out) {
    int idx = blockIdx.x * blockDim.x + threadIdx.x;
    if (idx >= NPTS * (C3 / 4)) return;
    int n = idx >> 5, cg = (idx & 31) * 4;
    float4 a = *(const float4*)&g_a2[cg];
    float4 c = *(const float4*)&g_c2[cg];
    float4 mx = *(const float4*)&g_pmax[n * C3 + cg];
    float4 mn = *(const float4*)&g_pmin[n * C3 + cg];
    float4 o;
    o.x = fmaxf(0.f, fmaf(a.x, (a.x > 0.f) ? mx.x : mn.x, c.x));
    o.y = fmaxf(0.f, fmaf(a.y, (a.y > 0.f) ? mx.y : mn.y, c.y));
    o.z = fmaxf(0.f, fmaf(a.z, (a.z > 0.f) ? mx.z : mn.z, c.z));
    o.w = fmaxf(0.f, fmaf(a.w, (a.w > 0.f) ? mx.w : mn.w, c.w));
    *(float4*)&out[(size_t)n * C3 + cg] = o;
}

// ---------------- host entry ------------------------------------------------
extern "C" void kernel_launch(void* const* d_in, const int* in_sizes, int n_in,
                              void* d_out, int out_size) {
    const float* center  = (const float*)d_in[0];
    const float* normal  = (const float*)d_in[1];
    const float* feature = (const float*)d_in[2];
    const int*   offset  = (const int*)d_in[3];
    const int*   gidx    = (const int*)d_in[4];
    const float* W0 = (const float*)d_in[5];
    const float* b0 = (const float*)d_in[6];
    const float* g0 = (const float*)d_in[7];
    const float* be0 = (const float*)d_in[8];
    const float* W1 = (const float*)d_in[9];
    const float* g1 = (const float*)d_in[11];
    const float* be1 = (const float*)d_in[12];
    const float* W2 = (const float*)d_in[13];
    const float* g2 = (const float*)d_in[15];
    const float* be2 = (const float*)d_in[16];

    float* out = (float*)d_out;
    bool full = (out_size >= 2 * NPTS * 3 + NPTS * C3 + 1);
    float* featBase = full ? out + 2 * NPTS * 3 : out;

    const int SMX = 2 * TILEH * 2;   // 32768 B double-buffered fp16 staging

    k_zero<<<1, 128>>>();
    if (full) k_copy<<<256, 256>>>(center, normal, offset, out, 1);

    k_pre<<<160, BLK>>>(center, normal, feature, W0, b0);
    k_l0stats<<<1184, BLK>>>(gidx);
    k_fin0<<<1, 64>>>(g0, be0);
    k_l1<<<444, 256, SMX>>>(gidx, W1);
    k_fin1<<<1, 64>>>(g1, be1);
    k_l2<<<148, 512, SMX>>>(W2);
    k_fin2<<<1, 128>>>(g2, be2);
    k_poolapply<<<5000, BLK>>>(featBase);
}

// round 8
// speedup vs baseline: 3.5362x; 1.0892x over previous
#include <cuda_runtime.h>
#include <cuda_fp16.h>
#include <cstdint>

#define NPTS 40000
#define NSAMP 32
#define STOT (NPTS * NSAMP)     // 1,280,000
#define C0IN 38
#define C1 64
#define C2 64
#define C3 128
#define BNEPS 1e-5f
#define BLK 256
#define NWARP 8
#define TM 128
#define NT1 (STOT / TM)         // 10000 tiles
#define TILEH (TM * 64)         // halves per staging tile (16 KB)

// ---------------- scratch ---------------------------------------------------
__device__ __align__(16) float g_A[NPTS * C1];
__device__ __align__(16) float g_B[NPTS * C1];
__device__ __align__(16) uint4 g_y1f[(size_t)NT1 * 1024];   // fragment-linear fp16 y1
__device__ __align__(16) float g_pmax[NPTS * C3];
__device__ __align__(16) float g_pmin[NPTS * C3];

__device__ float g_sum0[C1], g_sq0[C1];
__device__ float g_sum1[C2], g_sq1[C2];
__device__ float g_sum2[C3], g_sq2[C3];
__device__ __align__(16) float g_a0[C1], g_c0[C1];
__device__ __align__(16) float g_a1[C2], g_c1[C2];
__device__ __align__(16) float g_a2[C3], g_c2[C3];

// ---------------- helpers ---------------------------------------------------
__device__ __forceinline__ void ldsm4(uint32_t* a, const __half* p) {
    uint32_t sa = (uint32_t)__cvta_generic_to_shared(p);
    asm volatile("ldmatrix.sync.aligned.m8n8.x4.shared.b16 {%0,%1,%2,%3}, [%4];"
                 : "=r"(a[0]), "=r"(a[1]), "=r"(a[2]), "=r"(a[3]) : "r"(sa));
}
__device__ __forceinline__ void mma16(float* d, const uint32_t* a, const uint32_t* b) {
    asm volatile(
        "mma.sync.aligned.m16n8k16.row.col.f32.f16.f16.f32 "
        "{%0,%1,%2,%3}, {%4,%5,%6,%7}, {%8,%9}, {%0,%1,%2,%3};"
        : "+f"(d[0]), "+f"(d[1]), "+f"(d[2]), "+f"(d[3])
        : "r"(a[0]), "r"(a[1]), "r"(a[2]), "r"(a[3]), "r"(b[0]), "r"(b[1]));
}
__device__ __forceinline__ uint32_t packh2(float x, float y) {
    __half2 h = __floats2half2_rn(x, y);
    return *reinterpret_cast<uint32_t*>(&h);
}

__global__ void k_zero() {
    int t = threadIdx.x;
    if (t < C1) { g_sum0[t] = 0.f; g_sq0[t] = 0.f; g_sum1[t] = 0.f; g_sq1[t] = 0.f; }
    if (t < C3) { g_sum2[t] = 0.f; g_sq2[t] = 0.f; }
}

__global__ void k_copy(const float* __restrict__ center,
                       const float* __restrict__ normal,
                       const int* __restrict__ offset,
                       float* __restrict__ out, int writeOffsetSlot) {
    int i = blockIdx.x * blockDim.x + threadIdx.x;
    int stride = gridDim.x * blockDim.x;
    for (; i < 2 * NPTS * 3; i += stride) {
        out[i] = (i < NPTS * 3) ? center[i] : normal[i - NPTS * 3];
    }
    if (writeOffsetSlot && blockIdx.x == 0 && threadIdx.x == 0) {
        out[2 * NPTS * 3 + NPTS * C3] = (float)offset[0];
    }
}

// ---------------- per-point precompute A = W0*x+b0, B = W0c*center ---------
__global__ void k_pre(const float* __restrict__ center,
                      const float* __restrict__ normal,
                      const float* __restrict__ feature,
                      const float* __restrict__ W0,
                      const float* __restrict__ b0) {
    __shared__ __align__(16) float Wt[C0IN * C1];
    __shared__ float xs[NWARP][C0IN];
    int tid = threadIdx.x;
    for (int i = tid; i < C0IN * C1; i += BLK) {
        int o = i / C0IN, c = i % C0IN;
        Wt[c * C1 + o] = W0[i];
    }
    __syncthreads();
    int w = tid >> 5, lane = tid & 31;
    int o0 = 2 * lane;
    float bias0 = b0[o0], bias1 = b0[o0 + 1];
    int wg = blockIdx.x * NWARP + w, nW = gridDim.x * NWARP;
    for (int n = wg; n < NPTS; n += nW) {
        {
            float v;
            if (lane < 3)      v = center[n * 3 + lane];
            else if (lane < 6) v = normal[n * 3 + lane - 3];
            else               v = feature[n * 32 + lane - 6];
            xs[w][lane] = v;
            if (lane < C0IN - 32) xs[w][32 + lane] = feature[n * 32 + 26 + lane];
        }
        __syncwarp();
        float a0 = 0.f, a1 = 0.f, bp0 = 0.f, bp1 = 0.f;
        #pragma unroll
        for (int c = 0; c < C0IN; ++c) {
            float2 wv = *(const float2*)&Wt[c * C1 + o0];
            float x = xs[w][c];
            a0 += wv.x * x; a1 += wv.y * x;
            if (c < 3) { bp0 += wv.x * x; bp1 += wv.y * x; }
        }
        *(float2*)&g_A[n * C1 + o0] = make_float2(a0 + bias0, a1 + bias1);
        *(float2*)&g_B[n * C1 + o0] = make_float2(bp0, bp1);
        __syncwarp();
    }
}

// ---------------- layer-0 stats: y0 = A[j]-B[n] ----------------------------
__global__ void k_l0stats(const int* __restrict__ gidx) {
    __shared__ float sS[C1], sQ[C1];
    int tid = threadIdx.x;
    if (tid < C1) { sS[tid] = 0.f; sQ[tid] = 0.f; }
    __syncthreads();
    int w = tid >> 5, lane = tid & 31, c0 = 2 * lane;
    float s0 = 0.f, s1 = 0.f, q0 = 0.f, q1 = 0.f;
    int wg = blockIdx.x * NWARP + w, nW = gridDim.x * NWARP;
    for (int n = wg; n < NPTS; n += nW) {
        float2 bv = *(const float2*)&g_B[n * C1 + c0];
        int js = gidx[n * NSAMP + lane];
        #pragma unroll
        for (int s = 0; s < NSAMP; ++s) {
            int j = __shfl_sync(0xffffffffu, js, s);
            float2 av = *(const float2*)&g_A[j * C1 + c0];
            float y0 = av.x - bv.x, y1v = av.y - bv.y;
            s0 += y0; s1 += y1v; q0 += y0 * y0; q1 += y1v * y1v;
        }
    }
    atomicAdd(&sS[c0], s0); atomicAdd(&sS[c0 + 1], s1);
    atomicAdd(&sQ[c0], q0); atomicAdd(&sQ[c0 + 1], q1);
    __syncthreads();
    if (tid < C1) { atomicAdd(&g_sum0[tid], sS[tid]); atomicAdd(&g_sq0[tid], sQ[tid]); }
}

__global__ void k_fin0(const float* __restrict__ g, const float* __restrict__ be) {
    int t = threadIdx.x;
    if (t < C1) {
        float inv = 1.f / (float)STOT;
        float mean = g_sum0[t] * inv;
        float var = g_sq0[t] * inv - mean * mean;
        float a = g[t] * rsqrtf(var + BNEPS);
        g_a0[t] = a;
        g_c0[t] = fmaf(-a, mean, be[t]);
    }
}
__global__ void k_fin1(const float* __restrict__ g, const float* __restrict__ be) {
    int t = threadIdx.x;
    if (t < C2) {
        float inv = 1.f / (float)STOT;
        float mean = g_sum1[t] * inv;
        float var = g_sq1[t] * inv - mean * mean;
        float a = g[t] * rsqrtf(var + BNEPS);
        g_a1[t] = a;
        g_c1[t] = fmaf(-a, mean, be[t]);
    }
}
__global__ void k_fin2(const float* __restrict__ g, const float* __restrict__ be) {
    int t = threadIdx.x;
    if (t < C3) {
        float inv = 1.f / (float)STOT;
        float mean = g_sum2[t] * inv;
        float var = g_sq2[t] * inv - mean * mean;
        float a = g[t] * rsqrtf(var + BNEPS);
        g_a2[t] = a;
        g_c2[t] = fmaf(-a, mean, be[t]);
    }
}

// ---------------- coalesced gather staging (unchanged layout) --------------
__device__ __forceinline__ void stage1(__half* __restrict__ Xb, int tile, int w, int lane,
                                       const int* __restrict__ gidx,
                                       float4 a4, float4 c4) {
    int ch = lane & 15, hw = lane >> 4;
    int jreg = gidx[tile * TM + w * 16 + ch];
    int n = tile * 4 + (w >> 1);
    float4 bv = *(const float4*)&g_B[n * C1 + ch * 4];
    #pragma unroll
    for (int i = 0; i < 8; ++i) {
        int r = w * 16 + i * 2 + hw;
        int j = __shfl_sync(0xffffffffu, jreg, i * 2 + hw);
        float4 av = *(const float4*)&g_A[(size_t)j * C1 + ch * 4];
        float x0 = fmaxf(0.f, fmaf(a4.x, av.x - bv.x, c4.x));
        float x1 = fmaxf(0.f, fmaf(a4.y, av.y - bv.y, c4.y));
        float x2 = fmaxf(0.f, fmaf(a4.z, av.z - bv.z, c4.z));
        float x3 = fmaxf(0.f, fmaf(a4.w, av.w - bv.w, c4.w));
        uint32_t u0 = packh2(x0, x1), u1 = packh2(x2, x3);
        *(uint2*)(Xb + r * 64 + (((ch >> 1) ^ (r & 7)) << 3) + (ch & 1) * 4) = make_uint2(u0, u1);
    }
}

// ---------------- layer1: 8 warps, warp tile 32x32 (nf=4 reuse) ------------
__global__ void __launch_bounds__(256, 2)
k_l1(const int* __restrict__ gidx, const float* __restrict__ W1) {
    extern __shared__ __align__(16) __half X[];   // [2][TILEH]
    __shared__ float aS[C1], cS[C1];
    int tid = threadIdx.x;
    if (tid < C1) { aS[tid] = g_a0[tid]; cS[tid] = g_c0[tid]; }
    int w = tid >> 5, lane = tid & 31;
    int g = lane >> 2, t = lane & 3;
    int wm = w >> 1, wn = w & 1;          // rows wm*32..+31, cols wn*32..+31
    int sub = lane >> 3, ir = lane & 7;
    int rowoff = (sub & 1) * 8 + ir;
    int csel = sub >> 1;
    uint32_t Bf[4][4][2];
    #pragma unroll
    for (int nf = 0; nf < 4; ++nf)
        #pragma unroll
        for (int kf = 0; kf < 4; ++kf) {
            int n = wn * 32 + nf * 8 + g;
            const float* wr = W1 + n * C1 + kf * 16;
            Bf[nf][kf][0] = packh2(wr[2 * t], wr[2 * t + 1]);
            Bf[nf][kf][1] = packh2(wr[8 + 2 * t], wr[8 + 2 * t + 1]);
        }
    float sum[8] = {0}, sq[8] = {0};
    __syncthreads();
    int ch = lane & 15;
    float4 a4 = *(const float4*)&aS[ch * 4];
    float4 c4 = *(const float4*)&cS[ch * 4];

    int tile = blockIdx.x, buf = 0;
    stage1(X, tile, w, lane, gidx, a4, c4);
    for (; tile < NT1; tile += gridDim.x, buf ^= 1) {
        __syncthreads();
        int nxt = tile + gridDim.x;
        if (nxt < NT1) stage1(X + (buf ^ 1) * TILEH, nxt, w, lane, gidx, a4, c4);
        const __half* Xb = X + buf * TILEH;
        #pragma unroll
        for (int mf = 0; mf < 2; ++mf) {
            int rb = wm * 32 + mf * 16;
            float acc[4][4];
            #pragma unroll
            for (int nf = 0; nf < 4; ++nf)
                #pragma unroll
                for (int e = 0; e < 4; ++e) acc[nf][e] = 0.f;
            #pragma unroll
            for (int kf = 0; kf < 4; ++kf) {
                uint32_t Af[4];
                ldsm4(Af, Xb + (rb + rowoff) * 64 + (((2 * kf + csel) ^ ir) << 3));
                #pragma unroll
                for (int nf = 0; nf < 4; ++nf) mma16(acc[nf], Af, Bf[nf][kf]);
            }
            #pragma unroll
            for (int q = 0; q < 2; ++q) {
                uint4 pv;
                pv.x = packh2(acc[2 * q][0], acc[2 * q][1]);
                pv.y = packh2(acc[2 * q][2], acc[2 * q][3]);
                pv.z = packh2(acc[2 * q + 1][0], acc[2 * q + 1][1]);
                pv.w = packh2(acc[2 * q + 1][2], acc[2 * q + 1][3]);
                g_y1f[(size_t)tile * 1024 + w * 128 + mf * 64 + q * 32 + lane] = pv;
            }
            #pragma unroll
            for (int nf = 0; nf < 4; ++nf) {
                sum[nf * 2 + 0] += acc[nf][0] + acc[nf][2];
                sum[nf * 2 + 1] += acc[nf][1] + acc[nf][3];
                sq[nf * 2 + 0] += acc[nf][0] * acc[nf][0] + acc[nf][2] * acc[nf][2];
                sq[nf * 2 + 1] += acc[nf][1] * acc[nf][1] + acc[nf][3] * acc[nf][3];
            }
        }
    }
    #pragma unroll
    for (int sl = 0; sl < 8; ++sl) {
        float s = sum[sl], q = sq[sl];
        s += __shfl_xor_sync(~0u, s, 4);  q += __shfl_xor_sync(~0u, q, 4);
        s += __shfl_xor_sync(~0u, s, 8);  q += __shfl_xor_sync(~0u, q, 8);
        s += __shfl_xor_sync(~0u, s, 16); q += __shfl_xor_sync(~0u, q, 16);
        if (g == 0) {
            int col = wn * 32 + (sl >> 1) * 8 + 2 * t + (sl & 1);
            atomicAdd(&g_sum1[col], s);
            atomicAdd(&g_sq1[col], q);
        }
    }
}

// ---------------- layer2 staging: y1f -> BN1+relu -> swizzled tile ---------
__device__ __forceinline__ void stage2(__half* __restrict__ Xb, int tile, int tid,
                                       const float* aS, const float* cS) {
    #pragma unroll
    for (int it = 0; it < 4; ++it) {
        int u = tid + it * 256;
        int w1 = u >> 7, rem = u & 127;
        int mf1 = (rem >> 6) & 1, q = (rem >> 5) & 1, ln = u & 31;
        int gg = ln >> 2, tt = ln & 3;
        int wm1 = w1 >> 1, wn1 = w1 & 1;
        int rb = wm1 * 32 + mf1 * 16;
        int r0 = rb + gg, r1 = r0 + 8;
        int cp0 = wn1 * 16 + q * 8 + tt, cp1 = cp0 + 4;
        uint4 v = g_y1f[(size_t)tile * 1024 + u];
        float2 a0v = *(const float2*)&aS[2 * cp0], c0v = *(const float2*)&cS[2 * cp0];
        float2 a1v = *(const float2*)&aS[2 * cp1], c1v = *(const float2*)&cS[2 * cp1];
        float2 f;
        f = __half22float2(*(__half2*)&v.x);
        uint32_t u00 = packh2(fmaxf(0.f, fmaf(a0v.x, f.x, c0v.x)),
                              fmaxf(0.f, fmaf(a0v.y, f.y, c0v.y)));
        f = __half22float2(*(__half2*)&v.y);
        uint32_t u01 = packh2(fmaxf(0.f, fmaf(a0v.x, f.x, c0v.x)),
                              fmaxf(0.f, fmaf(a0v.y, f.y, c0v.y)));
        f = __half22float2(*(__half2*)&v.z);
        uint32_t u10 = packh2(fmaxf(0.f, fmaf(a1v.x, f.x, c1v.x)),
                              fmaxf(0.f, fmaf(a1v.y, f.y, c1v.y)));
        f = __half22float2(*(__half2*)&v.w);
        uint32_t u11 = packh2(fmaxf(0.f, fmaf(a1v.x, f.x, c1v.x)),
                              fmaxf(0.f, fmaf(a1v.y, f.y, c1v.y)));
        int ch0 = wn1 * 4 + q * 2, ch1 = ch0 + 1;
        *(uint32_t*)(Xb + r0 * 64 + ((ch0 ^ (r0 & 7)) << 3) + tt * 2) = u00;
        *(uint32_t*)(Xb + r1 * 64 + ((ch0 ^ (r1 & 7)) << 3) + tt * 2) = u01;
        *(uint32_t*)(Xb + r0 * 64 + ((ch1 ^ (r0 & 7)) << 3) + tt * 2) = u10;
        *(uint32_t*)(Xb + r1 * 64 + ((ch1 ^ (r1 & 7)) << 3) + tt * 2) = u11;
    }
}

// ---------------- layer2: 8 warps, warp tile 64x32 (nf=4 reuse) ------------
__global__ void __launch_bounds__(256, 2)
k_l2(const float* __restrict__ W2) {
    extern __shared__ __align__(16) __half X[];   // [2][TILEH]
    __shared__ float aS[C2], cS[C2];
    int tid = threadIdx.x;
    if (tid < C2) { aS[tid] = g_a1[tid]; cS[tid] = g_c1[tid]; }
    int w = tid >> 5, lane = tid & 31;
    int g = lane >> 2, t = lane & 3;
    int wm = w >> 2, wn = w & 3;          // rows wm*64..+63, cols wn*32..+31
    int sub = lane >> 3, ir = lane & 7;
    int rowoff = (sub & 1) * 8 + ir;
    int csel = sub >> 1;
    uint32_t Bf[4][4][2];
    #pragma unroll
    for (int nf = 0; nf < 4; ++nf)
        #pragma unroll
        for (int kf = 0; kf < 4; ++kf) {
            int n = wn * 32 + nf * 8 + g;
            const float* wr = W2 + n * C2 + kf * 16;
            Bf[nf][kf][0] = packh2(wr[2 * t], wr[2 * t + 1]);
            Bf[nf][kf][1] = packh2(wr[8 + 2 * t], wr[8 + 2 * t + 1]);
        }
    float sum[8] = {0}, sq[8] = {0};
    __syncthreads();

    int tile = blockIdx.x, buf = 0;
    stage2(X, tile, tid, aS, cS);
    for (; tile < NT1; tile += gridDim.x, buf ^= 1) {
        __syncthreads();
        int nxt = tile + gridDim.x;
        if (nxt < NT1) stage2(X + (buf ^ 1) * TILEH, nxt, tid, aS, cS);
        const __half* Xb = X + buf * TILEH;
        float mxx[2][8], mnn[2][8];
        #pragma unroll
        for (int ps = 0; ps < 2; ++ps)
            #pragma unroll
            for (int sl = 0; sl < 8; ++sl) { mxx[ps][sl] = -1e30f; mnn[ps][sl] = 1e30f; }
        #pragma unroll
        for (int mf = 0; mf < 4; ++mf) {
            int rb = wm * 64 + mf * 16;
            float acc[4][4];
            #pragma unroll
            for (int nf = 0; nf < 4; ++nf)
                #pragma unroll
                for (int e = 0; e < 4; ++e) acc[nf][e] = 0.f;
            #pragma unroll
            for (int kf = 0; kf < 4; ++kf) {
                uint32_t Af[4];
                ldsm4(Af, Xb + (rb + rowoff) * 64 + (((2 * kf + csel) ^ ir) << 3));
                #pragma unroll
                for (int nf = 0; nf < 4; ++nf) mma16(acc[nf], Af, Bf[nf][kf]);
            }
            int ps = mf >> 1;
            #pragma unroll
            for (int nf = 0; nf < 4; ++nf) {
                sum[nf * 2 + 0] += acc[nf][0] + acc[nf][2];
                sum[nf * 2 + 1] += acc[nf][1] + acc[nf][3];
                sq[nf * 2 + 0] += acc[nf][0] * acc[nf][0] + acc[nf][2] * acc[nf][2];
                sq[nf * 2 + 1] += acc[nf][1] * acc[nf][1] + acc[nf][3] * acc[nf][3];
                mxx[ps][nf * 2 + 0] = fmaxf(mxx[ps][nf * 2 + 0], fmaxf(acc[nf][0], acc[nf][2]));
                mxx[ps][nf * 2 + 1] = fmaxf(mxx[ps][nf * 2 + 1], fmaxf(acc[nf][1], acc[nf][3]));
                mnn[ps][nf * 2 + 0] = fminf(mnn[ps][nf * 2 + 0], fminf(acc[nf][0], acc[nf][2]));
                mnn[ps][nf * 2 + 1] = fminf(mnn[ps][nf * 2 + 1], fminf(acc[nf][1], acc[nf][3]));
            }
        }
        #pragma unroll
        for (int ps = 0; ps < 2; ++ps)
            #pragma unroll
            for (int sl = 0; sl < 8; ++sl) {
                float mx = mxx[ps][sl], mn = mnn[ps][sl];
                mx = fmaxf(mx, __shfl_xor_sync(~0u, mx, 4));
                mn = fminf(mn, __shfl_xor_sync(~0u, mn, 4));
                mx = fmaxf(mx, __shfl_xor_sync(~0u, mx, 8));
                mn = fminf(mn, __shfl_xor_sync(~0u, mn, 8));
                mx = fmaxf(mx, __shfl_xor_sync(~0u, mx, 16));
                mn = fminf(mn, __shfl_xor_sync(~0u, mn, 16));
                if (g == 0) {
                    int col = wn * 32 + (sl >> 1) * 8 + 2 * t + (sl & 1);
                    int n = tile * 4 + wm * 2 + ps;
                    g_pmax[n * C3 + col] = mx;
                    g_pmin[n * C3 + col] = mn;
                }
            }
    }
    #pragma unroll
    for (int sl = 0; sl < 8; ++sl) {
        float s = sum[sl], q = sq[sl];
        s += __shfl_xor_sync(~0u, s, 4);  q += __shfl_xor_sync(~0u, q, 4);
        s += __shfl_xor_sync(~0u, s, 8);  q += __shfl_xor_sync(~0u, q, 8);
        s += __shfl_xor_sync(~0u, s, 16); q += __shfl_xor_sync(~0u, q, 16);
        if (g == 0) {
            int col = wn * 32 + (sl >> 1) * 8 + 2 * t + (sl & 1);
            atomicAdd(&g_sum2[col], s);
            atomicAdd(&g_sq2[col], q);
        }
    }
}

// ---------------- epilogue: BN2+relu on pooled extrema ---------------------
__global__ void k_poolapply(float* __restrict__ out) {
    int idx = blockIdx.x * blockDim.x + threadIdx.x;
    if (idx >= NPTS * (C3 / 4)) return;
    int n = idx >> 5, cg = (idx & 31) * 4;
    float4 a = *(const float4*)&g_a2[cg];
    float4 c = *(const float4*)&g_c2[cg];
    float4 mx = *(const float4*)&g_pmax[n * C3 + cg];
    float4 mn = *(const float4*)&g_pmin[n * C3 + cg];
    float4 o;
    o.x = fmaxf(0.f, fmaf(a.x, (a.x > 0.f) ? mx.x : mn.x, c.x));
    o.y = fmaxf(0.f, fmaf(a.y, (a.y > 0.f) ? mx.y : mn.y, c.y));
    o.z = fmaxf(0.f, fmaf(a.z, (a.z > 0.f) ? mx.z : mn.z, c.z));
    o.w = fmaxf(0.f, fmaf(a.w, (a.w > 0.f) ? mx.w : mn.w, c.w));
    *(float4*)&out[(size_t)n * C3 + cg] = o;
}

// ---------------- host entry ------------------------------------------------
extern "C" void kernel_launch(void* const* d_in, const int* in_sizes, int n_in,
                              void* d_out, int out_size) {
    const float* center  = (const float*)d_in[0];
    const float* normal  = (const float*)d_in[1];
    const float* feature = (const float*)d_in[2];
    const int*   offset  = (const int*)d_in[3];
    const int*   gidx    = (const int*)d_in[4];
    const float* W0 = (const float*)d_in[5];
    const float* b0 = (const float*)d_in[6];
    const float* g0 = (const float*)d_in[7];
    const float* be0 = (const float*)d_in[8];
    const float* W1 = (const float*)d_in[9];
    const float* g1 = (const float*)d_in[11];
    const float* be1 = (const float*)d_in[12];
    const float* W2 = (const float*)d_in[13];
    const float* g2 = (const float*)d_in[15];
    const float* be2 = (const float*)d_in[16];

    float* out = (float*)d_out;
    bool full = (out_size >= 2 * NPTS * 3 + NPTS * C3 + 1);
    float* featBase = full ? out + 2 * NPTS * 3 : out;

    const int SMX = 2 * TILEH * 2;   // 32768 B double-buffered fp16 staging

    k_zero<<<1, 128>>>();
    if (full) k_copy<<<256, 256>>>(center, normal, offset, out, 1);

    k_pre<<<160, BLK>>>(center, normal, feature, W0, b0);
    k_l0stats<<<1184, BLK>>>(gidx);
    k_fin0<<<1, 64>>>(g0, be0);
    k_l1<<<296, 256, SMX>>>(gidx, W1);
    k_fin1<<<1, 64>>>(g1, be1);
    k_l2<<<296, 256, SMX>>>(W2);
    k_fin2<<<1, 128>>>(g2, be2);
    k_poolapply<<<5000, BLK>>>(featBase);
}